// round 10
// baseline (speedup 1.0000x reference)
#include <cuda_runtime.h>
#include <mma.h>
#include <cstdint>

using namespace nvcuda;

#define BB 4
#define SS 1024
#define DD 1024
#define HH 16
#define HD 64

// Scratch (__device__ globals — allocation-free rule)
static __device__ float g_q[BB * HH * SS * HD];
static __device__ float g_k[BB * HH * SS * HD];
static __device__ float g_v[BB * HH * SS * HD];
static __device__ float g_ao[BB * SS * DD];
static __device__ uint32_t g_mb[BB * SS * (SS / 32)];  // packed mask bits

__device__ __forceinline__ void cpa16(void* dst, const void* src) {
    unsigned d = (unsigned)__cvta_generic_to_shared(dst);
    asm volatile("cp.async.cg.shared.global [%0], [%1], 16;\n" :: "r"(d), "l"(src));
}
#define CP_COMMIT() asm volatile("cp.async.commit_group;\n" ::)
#define CP_WAIT(N)  asm volatile("cp.async.wait_group %0;\n" :: "n"(N))

#define TF32(x) wmma::__float_to_tf32(x)

// m16n8k8 tf32 mma (A row-major, B col-major), D/C fp32, accumulate in place
__device__ __forceinline__ void mma8(float* d, const float* a,
                                     float b0, float b1) {
    asm volatile(
        "mma.sync.aligned.m16n8k8.row.col.f32.tf32.tf32.f32 "
        "{%0,%1,%2,%3}, {%4,%5,%6,%7}, {%8,%9}, {%0,%1,%2,%3};"
        : "+f"(d[0]), "+f"(d[1]), "+f"(d[2]), "+f"(d[3])
        : "r"(__float_as_uint(a[0])), "r"(__float_as_uint(a[1])),
          "r"(__float_as_uint(a[2])), "r"(__float_as_uint(a[3])),
          "r"(__float_as_uint(b0)), "r"(__float_as_uint(b1)));
}

// ---------------------------------------------------------------------------
// pack 32 mask ints into one bit word; idx = (b*SS+q)*32 + w
// ---------------------------------------------------------------------------
__global__ void maskpack_k(const int* __restrict__ mask) {
    int idx = blockIdx.x * 256 + threadIdx.x;
    if (idx >= BB * SS * (SS / 32)) return;
    const int4* src = (const int4*)(mask + (size_t)idx * 32);
    uint32_t w = 0;
#pragma unroll
    for (int i = 0; i < 8; i++) {
        int4 v = src[i];
        w |= (v.x != 0 ? 1u : 0u) << (i * 4 + 0);
        w |= (v.y != 0 ? 1u : 0u) << (i * 4 + 1);
        w |= (v.z != 0 ? 1u : 0u) << (i * 4 + 2);
        w |= (v.w != 0 ? 1u : 0u) << (i * 4 + 3);
    }
    g_mb[idx] = w;
}

// ---------------------------------------------------------------------------
// Raw mma.sync tf32 GEMM. CTA tile 128x128, BK=32, 128 thr (4 warps 2x2,
// warp tile 64x64). 3-stage cp.async ring, one barrier per slab.
// RN tf32 rounding applied AT FRAGMENT LOAD (raw fp32 in smem).
// MODE 0: A=Ap(=x), B=Bp(=Wqkv) -> scatter q(*0.125, tf32)/k/v (tf32)
// MODE 1: A=g_ao (device-side symbol!), B=Bp(=Wo) -> C = acc + bias (fp32)
// Stage: A[128][36] (4608 f) + B[32][136] (4352 f) = 8960 f.
// ---------------------------------------------------------------------------
#define GSTG 8960
#define GSMEM (3 * GSTG * 4)

template <int MODE>
__global__ void __launch_bounds__(128, 2) mgemm_k(
    const float* __restrict__ Ain, const float* __restrict__ Bp,
    const float* __restrict__ bias, float* __restrict__ C, int N, int K)
{
    extern __shared__ float sm[];

    const int tid = threadIdx.x, lane = tid & 31, warp = tid >> 5;
    const int g = lane >> 2, tig = lane & 3;
    const int wm = (warp >> 1) * 64, wn = (warp & 1) * 64;
    const int m0 = blockIdx.y * 128, n0 = blockIdx.x * 128;

    // NOTE: g_ao must be resolved INSIDE the kernel (device symbol).
    const float* Ap = (MODE == 1) ? (const float*)g_ao : Ain;

    const int ar = tid >> 3, ac = (tid & 7) * 4;    // rows ar + v*16
    const int br = tid >> 5, bc = (tid & 31) * 4;   // rows br + v*4

    auto issue = [&](int st, int k0) {
        float* As = sm + st * GSTG;
        float* Bs = As + 4608;
#pragma unroll
        for (int v = 0; v < 8; v++)
            cpa16(&As[(ar + v * 16) * 36 + ac],
                  Ap + (size_t)(m0 + ar + v * 16) * K + k0 + ac);
#pragma unroll
        for (int v = 0; v < 8; v++)
            cpa16(&Bs[(br + v * 4) * 136 + bc],
                  Bp + (size_t)(k0 + br + v * 4) * N + n0 + bc);
    };

    float d[4][8][4];
#pragma unroll
    for (int mf = 0; mf < 4; mf++)
#pragma unroll
        for (int nf = 0; nf < 8; nf++)
#pragma unroll
            for (int c = 0; c < 4; c++) d[mf][nf][c] = 0.0f;

    issue(0, 0);  CP_COMMIT();
    issue(1, 32); CP_COMMIT();

    const int NI = K / 32;
    for (int i = 0; i < NI; i++) {
        const int st = i % 3;
        CP_WAIT(1);
        __syncthreads();
        if (i + 2 < NI) issue((i + 2) % 3, (i + 2) * 32);
        CP_COMMIT();

        const float* As = sm + st * GSTG;
        const float* Bs = As + 4608;

        float af[2][4][4], bf[2][8][2];
        auto ldA = [&](int buf, int kk) {
#pragma unroll
            for (int mf = 0; mf < 4; mf++) {
                const float* a0 = &As[(wm + mf * 16 + g) * 36 + kk * 8 + tig];
                const float* a1 = &As[(wm + mf * 16 + g + 8) * 36 + kk * 8 + tig];
                af[buf][mf][0] = TF32(a0[0]); af[buf][mf][1] = TF32(a1[0]);
                af[buf][mf][2] = TF32(a0[4]); af[buf][mf][3] = TF32(a1[4]);
            }
        };
        auto ldB = [&](int buf, int kk) {
#pragma unroll
            for (int nf = 0; nf < 8; nf++) {
                bf[buf][nf][0] =
                    TF32(Bs[(kk * 8 + tig) * 136 + wn + nf * 8 + g]);
                bf[buf][nf][1] =
                    TF32(Bs[(kk * 8 + tig + 4) * 136 + wn + nf * 8 + g]);
            }
        };
        ldA(0, 0); ldB(0, 0);
#pragma unroll
        for (int kk = 0; kk < 4; kk++) {
            const int cur = kk & 1;
            if (kk < 3) { ldA(cur ^ 1, kk + 1); ldB(cur ^ 1, kk + 1); }
#pragma unroll
            for (int mf = 0; mf < 4; mf++)
#pragma unroll
                for (int nf = 0; nf < 8; nf++)
                    mma8(d[mf][nf], af[cur][mf], bf[cur][nf][0], bf[cur][nf][1]);
        }
    }

    // ---- direct epilogue ----
#pragma unroll
    for (int mf = 0; mf < 4; mf++) {
        const int m = m0 + wm + mf * 16 + g;
        const int bb = m >> 10, srow = m & 1023;
#pragma unroll
        for (int nf = 0; nf < 8; nf++) {
            const int col0 = n0 + wn + nf * 8 + 2 * tig;
            const float b0 = bias[col0], b1 = bias[col0 + 1];
            float v0 = d[mf][nf][0] + b0, v1 = d[mf][nf][1] + b1;
            float v2 = d[mf][nf][2] + b0, v3 = d[mf][nf][3] + b1;

            if (MODE == 0) {
                const int h = col0 / 192;
                const int rr = col0 - h * 192;
                const int seg = rr >> 6;
                const int db = rr & 63;
                const size_t idx =
                    (((size_t)(bb * HH + h)) * SS + srow) * HD + db;
                float* dst = (seg == 0) ? g_q : (seg == 1) ? g_k : g_v;
                const float sc = (seg == 0) ? 0.125f : 1.0f;
                float2 w0 = make_float2(TF32(v0 * sc), TF32(v1 * sc));
                float2 w1 = make_float2(TF32(v2 * sc), TF32(v3 * sc));
                *(float2*)&dst[idx]          = w0;
                *(float2*)&dst[idx + 8 * HD] = w1;
            } else {
                float* dst = C + (size_t)m * N + col0;
                *(float2*)dst           = make_float2(v0, v1);
                *(float2*)(dst + 8 * N) = make_float2(v2, v3);
            }
        }
    }
}

// ---------------------------------------------------------------------------
// Flash attention FA2, mma.sync tf32. 128 thr (4 warps), q-block 128,
// warp q-tile 32 (2 m-frags). K pad 68, V pad 72 (both conflict-free).
// Bitmask masking from g_mb. shfl P transport, register O.
// smem floats: Qs[128][68]=8704 | Ks[2][64][68]=8704 | Vs[2][64][72]=9216
// ---------------------------------------------------------------------------
#define KLD 68
#define VLD 72
#define NT (SS / 64)
#define ATTN_SMEM (26624 * 4)

__global__ void __launch_bounds__(128, 2) attn_k(void)
{
    extern __shared__ float sm[];
    float* Qs = sm;
    float* Ks = sm + 8704;    // stage stride 4352
    float* Vs = sm + 17408;   // stage stride 4608

    const int tid = threadIdx.x, lane = tid & 31, warp = tid >> 5;
    const int g = lane >> 2, tig = lane & 3;
    const int q0 = blockIdx.x * 128;
    const int h = blockIdx.y, b = blockIdx.z;
    const size_t bh = (size_t)(b * HH + h);
    const float* qb = g_q + bh * SS * HD;
    const float* kb = g_k + bh * SS * HD;
    const float* vb = g_v + bh * SS * HD;

    // Q tile -> smem
#pragma unroll
    for (int j = 0; j < 16; j++) {
        int idx = tid + j * 128;
        int r = idx >> 4, c4 = idx & 15;
        *(float4*)&Qs[r * KLD + c4 * 4] =
            *(const float4*)(qb + (size_t)(q0 + r) * HD + c4 * 4);
    }
    // prefetch KV tile 0
#pragma unroll
    for (int j = 0; j < 8; j++) {
        int idx = tid + j * 128;
        int r = idx >> 4, c4 = idx & 15;
        cpa16(&Ks[r * KLD + c4 * 4], kb + (size_t)r * HD + c4 * 4);
        cpa16(&Vs[r * VLD + c4 * 4], vb + (size_t)r * HD + c4 * 4);
    }
    CP_COMMIT();
    __syncthreads();

    // warp owns q rows [32*warp, 32*warp+32): 2 m-frags
    const int rb = 32 * warp;
    float qf[2][8][4];
#pragma unroll
    for (int mf = 0; mf < 2; mf++) {
        const int r0 = rb + mf * 16 + g, r1 = r0 + 8;
#pragma unroll
        for (int kk = 0; kk < 8; kk++) {
            qf[mf][kk][0] = Qs[r0 * KLD + kk * 8 + tig];
            qf[mf][kk][1] = Qs[r1 * KLD + kk * 8 + tig];
            qf[mf][kk][2] = Qs[r0 * KLD + kk * 8 + tig + 4];
            qf[mf][kk][3] = Qs[r1 * KLD + kk * 8 + tig + 4];
        }
    }

    float o[2][8][4];
#pragma unroll
    for (int mf = 0; mf < 2; mf++)
#pragma unroll
        for (int j = 0; j < 8; j++)
#pragma unroll
            for (int c = 0; c < 4; c++) o[mf][j][c] = 0.0f;
    float mi[2][2], li[2][2];
#pragma unroll
    for (int mf = 0; mf < 2; mf++) {
        mi[mf][0] = mi[mf][1] = -1e30f;
        li[mf][0] = li[mf][1] = 0.0f;
    }

    // bitmask row pointers (words of 32 cols)
    const uint32_t* mb0 = g_mb + ((size_t)b * SS + (q0 + rb + g)) * 32;
    const uint32_t* mb1 = g_mb + ((size_t)b * SS + (q0 + rb + g + 8)) * 32;
    const uint32_t* mb2 = g_mb + ((size_t)b * SS + (q0 + rb + 16 + g)) * 32;
    const uint32_t* mb3 = g_mb + ((size_t)b * SS + (q0 + rb + 16 + g + 8)) * 32;

    const int l0 = (g << 2) | (tig >> 1);
    const int l1 = l0 + 2;
    const bool odd = tig & 1;

    for (int t = 0; t < NT; t++) {
        const int st = t & 1;
        if (t + 1 < NT) {
            const float* kb2 = kb + (size_t)(t + 1) * 64 * HD;
            const float* vb2 = vb + (size_t)(t + 1) * 64 * HD;
            float* Kd = Ks + (st ^ 1) * 4352;
            float* Vd = Vs + (st ^ 1) * 4608;
#pragma unroll
            for (int j = 0; j < 8; j++) {
                int idx = tid + j * 128;
                int rr = idx >> 4, c4 = idx & 15;
                cpa16(&Kd[rr * KLD + c4 * 4], kb2 + (size_t)rr * HD + c4 * 4);
                cpa16(&Vd[rr * VLD + c4 * 4], vb2 + (size_t)rr * HD + c4 * 4);
            }
        }
        CP_COMMIT();

        // mask words for this tile (2 words per row)
        uint2 mw[4];
        mw[0] = *(const uint2*)(mb0 + t * 2);
        mw[1] = *(const uint2*)(mb1 + t * 2);
        mw[2] = *(const uint2*)(mb2 + t * 2);
        mw[3] = *(const uint2*)(mb3 + t * 2);

        CP_WAIT(1);
        __syncthreads();

        const float* Kst = Ks + st * 4352;
        const float* Vst = Vs + st * 4608;

        // ---- S = Q @ K^T (both m-frags share each K b-frag) ----
        float s[2][8][4];
#pragma unroll
        for (int j = 0; j < 8; j++) {
            s[0][j][0] = s[0][j][1] = s[0][j][2] = s[0][j][3] = 0.0f;
            s[1][j][0] = s[1][j][1] = s[1][j][2] = s[1][j][3] = 0.0f;
            const float* krow = &Kst[(j * 8 + g) * KLD];
#pragma unroll
            for (int kk = 0; kk < 8; kk++) {
                const float b0 = krow[kk * 8 + tig];
                const float b1 = krow[kk * 8 + tig + 4];
                mma8(s[0][j], qf[0][kk], b0, b1);
                mma8(s[1][j], qf[1][kk], b0, b1);
            }
        }

        // ---- bitmask ----
#pragma unroll
        for (int mf = 0; mf < 2; mf++) {
#pragma unroll
            for (int j = 0; j < 8; j++) {
                const int bit = (j * 8 + 2 * tig) & 31;
                const uint32_t wa = (j < 4) ? mw[mf * 2].x     : mw[mf * 2].y;
                const uint32_t wb = (j < 4) ? mw[mf * 2 + 1].x : mw[mf * 2 + 1].y;
                if (!((wa >> bit) & 1))       s[mf][j][0] = -1e20f;
                if (!((wa >> (bit + 1)) & 1)) s[mf][j][1] = -1e20f;
                if (!((wb >> bit) & 1))       s[mf][j][2] = -1e20f;
                if (!((wb >> (bit + 1)) & 1)) s[mf][j][3] = -1e20f;
            }
        }

        // ---- online softmax per m-frag ----
#pragma unroll
        for (int mf = 0; mf < 2; mf++) {
            float mx0 = s[mf][0][0], mx1 = s[mf][0][2];
#pragma unroll
            for (int j = 0; j < 8; j++) {
                mx0 = fmaxf(mx0, fmaxf(s[mf][j][0], s[mf][j][1]));
                mx1 = fmaxf(mx1, fmaxf(s[mf][j][2], s[mf][j][3]));
            }
            mx0 = fmaxf(mx0, __shfl_xor_sync(0xffffffffu, mx0, 1));
            mx0 = fmaxf(mx0, __shfl_xor_sync(0xffffffffu, mx0, 2));
            mx1 = fmaxf(mx1, __shfl_xor_sync(0xffffffffu, mx1, 1));
            mx1 = fmaxf(mx1, __shfl_xor_sync(0xffffffffu, mx1, 2));
            const float mn0 = fmaxf(mi[mf][0], mx0);
            const float mn1 = fmaxf(mi[mf][1], mx1);
            const float a0 = __expf(mi[mf][0] - mn0);
            const float a1 = __expf(mi[mf][1] - mn1);
            float rs0 = 0.0f, rs1 = 0.0f;
#pragma unroll
            for (int j = 0; j < 8; j++) {
                s[mf][j][0] = __expf(s[mf][j][0] - mn0);
                s[mf][j][1] = __expf(s[mf][j][1] - mn0);
                s[mf][j][2] = __expf(s[mf][j][2] - mn1);
                s[mf][j][3] = __expf(s[mf][j][3] - mn1);
                rs0 += s[mf][j][0] + s[mf][j][1];
                rs1 += s[mf][j][2] + s[mf][j][3];
            }
            rs0 += __shfl_xor_sync(0xffffffffu, rs0, 1);
            rs0 += __shfl_xor_sync(0xffffffffu, rs0, 2);
            rs1 += __shfl_xor_sync(0xffffffffu, rs1, 1);
            rs1 += __shfl_xor_sync(0xffffffffu, rs1, 2);
            li[mf][0] = li[mf][0] * a0 + rs0;
            li[mf][1] = li[mf][1] * a1 + rs1;
            mi[mf][0] = mn0; mi[mf][1] = mn1;
#pragma unroll
            for (int j = 0; j < 8; j++) {
                o[mf][j][0] *= a0; o[mf][j][1] *= a0;
                o[mf][j][2] *= a1; o[mf][j][3] *= a1;
                s[mf][j][0] = TF32(s[mf][j][0]);
                s[mf][j][1] = TF32(s[mf][j][1]);
                s[mf][j][2] = TF32(s[mf][j][2]);
                s[mf][j][3] = TF32(s[mf][j][3]);
            }
        }

        // ---- O += P @ V (V b-frags shared across m-frags) ----
#pragma unroll
        for (int kk = 0; kk < 8; kk++) {
            float pa0[4], pa1[4];
            {
                float u0 = __shfl_sync(0xffffffffu, s[0][kk][0], l0);
                float u1 = __shfl_sync(0xffffffffu, s[0][kk][1], l0);
                float u2 = __shfl_sync(0xffffffffu, s[0][kk][2], l0);
                float u3 = __shfl_sync(0xffffffffu, s[0][kk][3], l0);
                float w0 = __shfl_sync(0xffffffffu, s[0][kk][0], l1);
                float w1 = __shfl_sync(0xffffffffu, s[0][kk][1], l1);
                float w2 = __shfl_sync(0xffffffffu, s[0][kk][2], l1);
                float w3 = __shfl_sync(0xffffffffu, s[0][kk][3], l1);
                pa0[0] = odd ? u1 : u0; pa0[1] = odd ? u3 : u2;
                pa0[2] = odd ? w1 : w0; pa0[3] = odd ? w3 : w2;
            }
            {
                float u0 = __shfl_sync(0xffffffffu, s[1][kk][0], l0);
                float u1 = __shfl_sync(0xffffffffu, s[1][kk][1], l0);
                float u2 = __shfl_sync(0xffffffffu, s[1][kk][2], l0);
                float u3 = __shfl_sync(0xffffffffu, s[1][kk][3], l0);
                float w0 = __shfl_sync(0xffffffffu, s[1][kk][0], l1);
                float w1 = __shfl_sync(0xffffffffu, s[1][kk][1], l1);
                float w2 = __shfl_sync(0xffffffffu, s[1][kk][2], l1);
                float w3 = __shfl_sync(0xffffffffu, s[1][kk][3], l1);
                pa1[0] = odd ? u1 : u0; pa1[1] = odd ? u3 : u2;
                pa1[2] = odd ? w1 : w0; pa1[3] = odd ? w3 : w2;
            }
            const float* v0 = &Vst[(kk * 8 + tig) * VLD];
            const float* v1 = &Vst[(kk * 8 + tig + 4) * VLD];
#pragma unroll
            for (int j = 0; j < 8; j++) {
                const float b0 = v0[j * 8 + g];
                const float b1 = v1[j * 8 + g];
                mma8(o[0][j], pa0, b0, b1);
                mma8(o[1][j], pa1, b0, b1);
            }
        }
        __syncthreads();
    }

    // ---- normalize + write (out-proj rounds its own A-frags) ----
#pragma unroll
    for (int mf = 0; mf < 2; mf++) {
        const int r0 = rb + mf * 16 + g, r1 = r0 + 8;
        const float inv0 = 1.0f / li[mf][0], inv1 = 1.0f / li[mf][1];
        float* dst0 = g_ao + ((size_t)b * SS + (q0 + r0)) * DD + h * HD;
        float* dst1 = g_ao + ((size_t)b * SS + (q0 + r1)) * DD + h * HD;
#pragma unroll
        for (int j = 0; j < 8; j++) {
            float2 w0 = make_float2(o[mf][j][0] * inv0, o[mf][j][1] * inv0);
            float2 w1 = make_float2(o[mf][j][2] * inv1, o[mf][j][3] * inv1);
            *(float2*)&dst0[j * 8 + 2 * tig] = w0;
            *(float2*)&dst1[j * 8 + 2 * tig] = w1;
        }
    }
}

// ---------------------------------------------------------------------------
extern "C" void kernel_launch(void* const* d_in, const int* in_sizes, int n_in,
                              void* d_out, int out_size)
{
    const float* x    = (const float*)d_in[0];
    const int*   mask = (const int*)  d_in[1];
    const float* Wqkv = (const float*)d_in[2];
    const float* bqkv = (const float*)d_in[3];
    const float* Wo   = (const float*)d_in[4];
    const float* bo   = (const float*)d_in[5];
    float* out = (float*)d_out;
    (void)in_sizes; (void)n_in; (void)out_size;

    cudaFuncSetAttribute(attn_k, cudaFuncAttributeMaxDynamicSharedMemorySize,
                         ATTN_SMEM);
    cudaFuncSetAttribute(mgemm_k<0>, cudaFuncAttributeMaxDynamicSharedMemorySize,
                         GSMEM);
    cudaFuncSetAttribute(mgemm_k<1>, cudaFuncAttributeMaxDynamicSharedMemorySize,
                         GSMEM);

    // 0) mask bit-packing (only remaining pre-pass)
    maskpack_k<<<(BB * SS * (SS / 32) + 255) / 256, 256>>>(mask);

    // 1) QKV projection (raw x/Wqkv; tf32 RN at fragment load) -> q/k/v
    {
        dim3 grid(3 * DD / 128, (BB * SS) / 128);
        mgemm_k<0><<<grid, 128, GSMEM>>>(x, Wqkv, bqkv, nullptr, 3 * DD, DD);
    }

    // 2) Flash attention -> g_ao
    attn_k<<<dim3(SS / 128, HH, BB), 128, ATTN_SMEM>>>();

    // 3) Output projection -> d_out (A = g_ao resolved in-kernel)
    {
        dim3 grid(DD / 128, (BB * SS) / 128);
        mgemm_k<1><<<grid, 128, GSMEM>>>(nullptr, Wo, bo, out, DD, DD);
    }
}

// round 11
// speedup vs baseline: 1.0572x; 1.0572x over previous
#include <cuda_runtime.h>
#include <mma.h>
#include <cstdint>

using namespace nvcuda;

#define BB 4
#define SS 1024
#define DD 1024
#define HH 16
#define HD 64

// Scratch (__device__ globals — allocation-free rule)
static __device__ float g_q[BB * HH * SS * HD];
static __device__ float g_k[BB * HH * SS * HD];
static __device__ float g_v[BB * HH * SS * HD];
static __device__ float g_ao[BB * SS * DD];
static __device__ float g_xr[BB * SS * DD];       // tf32-rounded x
static __device__ float g_wqkvr[DD * 3 * DD];     // tf32-rounded Wqkv [K][N]
static __device__ float g_wor[DD * DD];           // tf32-rounded Wo   [K][N]
static __device__ uint32_t g_mb[BB * SS * (SS / 32)];  // packed mask bits

__device__ __forceinline__ void cpa16(void* dst, const void* src) {
    unsigned d = (unsigned)__cvta_generic_to_shared(dst);
    asm volatile("cp.async.cg.shared.global [%0], [%1], 16;\n" :: "r"(d), "l"(src));
}
#define CP_COMMIT() asm volatile("cp.async.commit_group;\n" ::)
#define CP_WAIT(N)  asm volatile("cp.async.wait_group %0;\n" :: "n"(N))

#define TF32(x) wmma::__float_to_tf32(x)

// m16n8k8 tf32 mma (A row-major, B col-major), D/C fp32, accumulate in place
__device__ __forceinline__ void mma8(float* d, const float* a,
                                     float b0, float b1) {
    asm volatile(
        "mma.sync.aligned.m16n8k8.row.col.f32.tf32.tf32.f32 "
        "{%0,%1,%2,%3}, {%4,%5,%6,%7}, {%8,%9}, {%0,%1,%2,%3};"
        : "+f"(d[0]), "+f"(d[1]), "+f"(d[2]), "+f"(d[3])
        : "r"(__float_as_uint(a[0])), "r"(__float_as_uint(a[1])),
          "r"(__float_as_uint(a[2])), "r"(__float_as_uint(a[3])),
          "r"(__float_as_uint(b0)), "r"(__float_as_uint(b1)));
}

// ---------------------------------------------------------------------------
// Fused pre-pass: one launch does tf32 rounding of x / Wqkv / Wo and mask
// bit-packing, switched on the flat index.
//   [0,      1048576)  : x      -> g_xr      (float4 units)
//   [1048576,1835008)  : Wqkv   -> g_wqkvr
//   [1835008,2097152)  : Wo     -> g_wor
//   [2097152,2228224)  : mask words -> g_mb
// ---------------------------------------------------------------------------
#define N4_X  (BB * SS * DD / 4)            // 1048576
#define N4_WQ (3 * DD * DD / 4)             // 786432
#define N4_WO (DD * DD / 4)                 // 262144
#define N_MW  (BB * SS * (SS / 32))         // 131072
#define PRE_TOT (N4_X + N4_WQ + N4_WO + N_MW)

__global__ void prepass_k(const float4* __restrict__ x,
                          const float4* __restrict__ Wqkv,
                          const float4* __restrict__ Wo,
                          const int* __restrict__ mask)
{
    int i = blockIdx.x * 256 + threadIdx.x;
    if (i < N4_X + N4_WQ + N4_WO) {
        const float4* src;
        float4* dst;
        if (i < N4_X)                  { src = x + i;                 dst = (float4*)g_xr + i; }
        else if (i < N4_X + N4_WQ)     { src = Wqkv + (i - N4_X);     dst = (float4*)g_wqkvr + (i - N4_X); }
        else                           { src = Wo + (i - N4_X - N4_WQ); dst = (float4*)g_wor + (i - N4_X - N4_WQ); }
        float4 v = *src;
        v.x = TF32(v.x); v.y = TF32(v.y); v.z = TF32(v.z); v.w = TF32(v.w);
        *dst = v;
    } else if (i < PRE_TOT) {
        int m = i - (N4_X + N4_WQ + N4_WO);
        const int4* src = (const int4*)(mask + (size_t)m * 32);
        uint32_t w = 0;
#pragma unroll
        for (int k = 0; k < 8; k++) {
            int4 v = src[k];
            w |= (v.x != 0 ? 1u : 0u) << (k * 4 + 0);
            w |= (v.y != 0 ? 1u : 0u) << (k * 4 + 1);
            w |= (v.z != 0 ? 1u : 0u) << (k * 4 + 2);
            w |= (v.w != 0 ? 1u : 0u) << (k * 4 + 3);
        }
        g_mb[m] = w;
    }
}

// ---------------------------------------------------------------------------
// Raw mma.sync tf32 GEMM (round-8 version). CTA tile 128x128, BK=32, 128 thr
// (4 warps 2x2, warp tile 64x64). 3-stage cp.async ring, 1 barrier/slab.
// Operands are pre-rounded; no cvt in the inner loop.
// Stage: A[128][36] (4608 f) + B[32][136] (4352 f) = 8960 f.
// MODE 0: A=g_xr, B=g_wqkvr -> scatter q(*0.125, tf32)/k/v (tf32)
// MODE 1: A=g_ao, B=g_wor -> C = acc + bias (fp32)
// ---------------------------------------------------------------------------
#define GSTG 8960
#define GSMEM (3 * GSTG * 4)

template <int MODE>
__global__ void __launch_bounds__(128, 2) mgemm_k(
    const float* __restrict__ bias, float* __restrict__ C, int N, int K)
{
    extern __shared__ float sm[];

    const int tid = threadIdx.x, lane = tid & 31, warp = tid >> 5;
    const int g = lane >> 2, tig = lane & 3;
    const int wm = (warp >> 1) * 64, wn = (warp & 1) * 64;
    const int m0 = blockIdx.y * 128, n0 = blockIdx.x * 128;

    const float* Ap = (MODE == 0) ? (const float*)g_xr    : (const float*)g_ao;
    const float* Bp = (MODE == 0) ? (const float*)g_wqkvr : (const float*)g_wor;

    const int ar = tid >> 3, ac = (tid & 7) * 4;    // rows ar + v*16
    const int br = tid >> 5, bc = (tid & 31) * 4;   // rows br + v*4

    auto issue = [&](int st, int k0) {
        float* As = sm + st * GSTG;
        float* Bs = As + 4608;
#pragma unroll
        for (int v = 0; v < 8; v++)
            cpa16(&As[(ar + v * 16) * 36 + ac],
                  Ap + (size_t)(m0 + ar + v * 16) * K + k0 + ac);
#pragma unroll
        for (int v = 0; v < 8; v++)
            cpa16(&Bs[(br + v * 4) * 136 + bc],
                  Bp + (size_t)(k0 + br + v * 4) * N + n0 + bc);
    };

    float d[4][8][4];
#pragma unroll
    for (int mf = 0; mf < 4; mf++)
#pragma unroll
        for (int nf = 0; nf < 8; nf++)
#pragma unroll
            for (int c = 0; c < 4; c++) d[mf][nf][c] = 0.0f;

    issue(0, 0);  CP_COMMIT();
    issue(1, 32); CP_COMMIT();

    const int NI = K / 32;
    for (int i = 0; i < NI; i++) {
        const int st = i % 3;
        CP_WAIT(1);
        __syncthreads();
        if (i + 2 < NI) issue((i + 2) % 3, (i + 2) * 32);
        CP_COMMIT();

        const float* As = sm + st * GSTG;
        const float* Bs = As + 4608;

        float af[2][4][4], bf[2][8][2];
        auto ldA = [&](int buf, int kk) {
#pragma unroll
            for (int mf = 0; mf < 4; mf++) {
                const float* a0 = &As[(wm + mf * 16 + g) * 36 + kk * 8 + tig];
                const float* a1 = &As[(wm + mf * 16 + g + 8) * 36 + kk * 8 + tig];
                af[buf][mf][0] = a0[0]; af[buf][mf][1] = a1[0];
                af[buf][mf][2] = a0[4]; af[buf][mf][3] = a1[4];
            }
        };
        auto ldB = [&](int buf, int kk) {
#pragma unroll
            for (int nf = 0; nf < 8; nf++) {
                bf[buf][nf][0] = Bs[(kk * 8 + tig) * 136 + wn + nf * 8 + g];
                bf[buf][nf][1] = Bs[(kk * 8 + tig + 4) * 136 + wn + nf * 8 + g];
            }
        };
        ldA(0, 0); ldB(0, 0);
#pragma unroll
        for (int kk = 0; kk < 4; kk++) {
            const int cur = kk & 1;
            if (kk < 3) { ldA(cur ^ 1, kk + 1); ldB(cur ^ 1, kk + 1); }
#pragma unroll
            for (int mf = 0; mf < 4; mf++)
#pragma unroll
                for (int nf = 0; nf < 8; nf++)
                    mma8(d[mf][nf], af[cur][mf], bf[cur][nf][0], bf[cur][nf][1]);
        }
    }

    // ---- direct epilogue ----
#pragma unroll
    for (int mf = 0; mf < 4; mf++) {
        const int m = m0 + wm + mf * 16 + g;
        const int bb = m >> 10, srow = m & 1023;
#pragma unroll
        for (int nf = 0; nf < 8; nf++) {
            const int col0 = n0 + wn + nf * 8 + 2 * tig;
            const float b0 = bias[col0], b1 = bias[col0 + 1];
            float v0 = d[mf][nf][0] + b0, v1 = d[mf][nf][1] + b1;
            float v2 = d[mf][nf][2] + b0, v3 = d[mf][nf][3] + b1;

            if (MODE == 0) {
                const int h = col0 / 192;
                const int rr = col0 - h * 192;
                const int seg = rr >> 6;
                const int db = rr & 63;
                const size_t idx =
                    (((size_t)(bb * HH + h)) * SS + srow) * HD + db;
                float* dst = (seg == 0) ? g_q : (seg == 1) ? g_k : g_v;
                const float sc = (seg == 0) ? 0.125f : 1.0f;
                float2 w0 = make_float2(TF32(v0 * sc), TF32(v1 * sc));
                float2 w1 = make_float2(TF32(v2 * sc), TF32(v3 * sc));
                *(float2*)&dst[idx]          = w0;
                *(float2*)&dst[idx + 8 * HD] = w1;
            } else {
                float* dst = C + (size_t)m * N + col0;
                *(float2*)dst           = make_float2(v0, v1);
                *(float2*)(dst + 8 * N) = make_float2(v2, v3);
            }
        }
    }
}

// ---------------------------------------------------------------------------
// Flash attention FA2, mma.sync tf32. 128 thr (4 warps), q-block 128,
// warp q-tile 32 (2 m-frags). K pad 68, V pad 72 (conflict-free).
// P transport now goes through the DEAD Qs buffer (smem, warp-private rows,
// __syncwarp only) instead of 128 shfl + 64 sel per tile per thread.
// smem floats: Qs[128][68]=8704 | Ks[2][64][68]=8704 | Vs[2][64][72]=9216
// ---------------------------------------------------------------------------
#define KLD 68
#define VLD 72
#define NT (SS / 64)
#define ATTN_SMEM (26624 * 4)

__global__ void __launch_bounds__(128, 2) attn_k(void)
{
    extern __shared__ float sm[];
    float* Qs = sm;           // q staging, then reused as P buffer
    float* Ks = sm + 8704;    // stage stride 4352
    float* Vs = sm + 17408;   // stage stride 4608

    const int tid = threadIdx.x, lane = tid & 31, warp = tid >> 5;
    const int g = lane >> 2, tig = lane & 3;
    const int q0 = blockIdx.x * 128;
    const int h = blockIdx.y, b = blockIdx.z;
    const size_t bh = (size_t)(b * HH + h);
    const float* qb = g_q + bh * SS * HD;
    const float* kb = g_k + bh * SS * HD;
    const float* vb = g_v + bh * SS * HD;

    // Q tile -> smem
#pragma unroll
    for (int j = 0; j < 16; j++) {
        int idx = tid + j * 128;
        int r = idx >> 4, c4 = idx & 15;
        *(float4*)&Qs[r * KLD + c4 * 4] =
            *(const float4*)(qb + (size_t)(q0 + r) * HD + c4 * 4);
    }
    // prefetch KV tile 0
#pragma unroll
    for (int j = 0; j < 8; j++) {
        int idx = tid + j * 128;
        int r = idx >> 4, c4 = idx & 15;
        cpa16(&Ks[r * KLD + c4 * 4], kb + (size_t)r * HD + c4 * 4);
        cpa16(&Vs[r * VLD + c4 * 4], vb + (size_t)r * HD + c4 * 4);
    }
    CP_COMMIT();
    __syncthreads();

    // warp owns q rows [32*warp, 32*warp+32): 2 m-frags
    const int rb = 32 * warp;
    const int r0a = rb + g,      r1a = rb + g + 8;      // mf 0 rows
    const int r0b = rb + 16 + g, r1b = rb + 16 + g + 8; // mf 1 rows

    float qf[2][8][4];
#pragma unroll
    for (int mf = 0; mf < 2; mf++) {
        const int r0 = rb + mf * 16 + g, r1 = r0 + 8;
#pragma unroll
        for (int kk = 0; kk < 8; kk++) {
            qf[mf][kk][0] = Qs[r0 * KLD + kk * 8 + tig];
            qf[mf][kk][1] = Qs[r1 * KLD + kk * 8 + tig];
            qf[mf][kk][2] = Qs[r0 * KLD + kk * 8 + tig + 4];
            qf[mf][kk][3] = Qs[r1 * KLD + kk * 8 + tig + 4];
        }
    }
    __syncthreads();   // everyone done reading Q; Qs is now the P buffer

    float o[2][8][4];
#pragma unroll
    for (int mf = 0; mf < 2; mf++)
#pragma unroll
        for (int j = 0; j < 8; j++)
#pragma unroll
            for (int c = 0; c < 4; c++) o[mf][j][c] = 0.0f;
    float mi[2][2], li[2][2];
#pragma unroll
    for (int mf = 0; mf < 2; mf++) {
        mi[mf][0] = mi[mf][1] = -1e30f;
        li[mf][0] = li[mf][1] = 0.0f;
    }

    // bitmask row pointers (words of 32 cols)
    const uint32_t* mb0 = g_mb + ((size_t)b * SS + (q0 + r0a)) * 32;
    const uint32_t* mb1 = g_mb + ((size_t)b * SS + (q0 + r1a)) * 32;
    const uint32_t* mb2 = g_mb + ((size_t)b * SS + (q0 + r0b)) * 32;
    const uint32_t* mb3 = g_mb + ((size_t)b * SS + (q0 + r1b)) * 32;

    for (int t = 0; t < NT; t++) {
        const int st = t & 1;
        if (t + 1 < NT) {
            const float* kb2 = kb + (size_t)(t + 1) * 64 * HD;
            const float* vb2 = vb + (size_t)(t + 1) * 64 * HD;
            float* Kd = Ks + (st ^ 1) * 4352;
            float* Vd = Vs + (st ^ 1) * 4608;
#pragma unroll
            for (int j = 0; j < 8; j++) {
                int idx = tid + j * 128;
                int rr = idx >> 4, c4 = idx & 15;
                cpa16(&Kd[rr * KLD + c4 * 4], kb2 + (size_t)rr * HD + c4 * 4);
                cpa16(&Vd[rr * VLD + c4 * 4], vb2 + (size_t)rr * HD + c4 * 4);
            }
        }
        CP_COMMIT();

        // mask words for this tile (2 words per row)
        uint2 mw[4];
        mw[0] = *(const uint2*)(mb0 + t * 2);
        mw[1] = *(const uint2*)(mb1 + t * 2);
        mw[2] = *(const uint2*)(mb2 + t * 2);
        mw[3] = *(const uint2*)(mb3 + t * 2);

        CP_WAIT(1);
        __syncthreads();

        const float* Kst = Ks + st * 4352;
        const float* Vst = Vs + st * 4608;

        // ---- S = Q @ K^T (both m-frags share each K b-frag) ----
        float s[2][8][4];
#pragma unroll
        for (int j = 0; j < 8; j++) {
            s[0][j][0] = s[0][j][1] = s[0][j][2] = s[0][j][3] = 0.0f;
            s[1][j][0] = s[1][j][1] = s[1][j][2] = s[1][j][3] = 0.0f;
            const float* krow = &Kst[(j * 8 + g) * KLD];
#pragma unroll
            for (int kk = 0; kk < 8; kk++) {
                const float b0 = krow[kk * 8 + tig];
                const float b1 = krow[kk * 8 + tig + 4];
                mma8(s[0][j], qf[0][kk], b0, b1);
                mma8(s[1][j], qf[1][kk], b0, b1);
            }
        }

        // ---- bitmask ----
#pragma unroll
        for (int mf = 0; mf < 2; mf++) {
#pragma unroll
            for (int j = 0; j < 8; j++) {
                const int bit = (j * 8 + 2 * tig) & 31;
                const uint32_t wa = (j < 4) ? mw[mf * 2].x     : mw[mf * 2].y;
                const uint32_t wb = (j < 4) ? mw[mf * 2 + 1].x : mw[mf * 2 + 1].y;
                if (!((wa >> bit) & 1))       s[mf][j][0] = -1e20f;
                if (!((wa >> (bit + 1)) & 1)) s[mf][j][1] = -1e20f;
                if (!((wb >> bit) & 1))       s[mf][j][2] = -1e20f;
                if (!((wb >> (bit + 1)) & 1)) s[mf][j][3] = -1e20f;
            }
        }

        // ---- online softmax per m-frag; write tf32 P to smem (Qs reuse) ----
#pragma unroll
        for (int mf = 0; mf < 2; mf++) {
            float mx0 = s[mf][0][0], mx1 = s[mf][0][2];
#pragma unroll
            for (int j = 0; j < 8; j++) {
                mx0 = fmaxf(mx0, fmaxf(s[mf][j][0], s[mf][j][1]));
                mx1 = fmaxf(mx1, fmaxf(s[mf][j][2], s[mf][j][3]));
            }
            mx0 = fmaxf(mx0, __shfl_xor_sync(0xffffffffu, mx0, 1));
            mx0 = fmaxf(mx0, __shfl_xor_sync(0xffffffffu, mx0, 2));
            mx1 = fmaxf(mx1, __shfl_xor_sync(0xffffffffu, mx1, 1));
            mx1 = fmaxf(mx1, __shfl_xor_sync(0xffffffffu, mx1, 2));
            const float mn0 = fmaxf(mi[mf][0], mx0);
            const float mn1 = fmaxf(mi[mf][1], mx1);
            const float a0 = __expf(mi[mf][0] - mn0);
            const float a1 = __expf(mi[mf][1] - mn1);
            float rs0 = 0.0f, rs1 = 0.0f;
            const int rr0 = rb + mf * 16 + g, rr1 = rr0 + 8;
#pragma unroll
            for (int j = 0; j < 8; j++) {
                s[mf][j][0] = __expf(s[mf][j][0] - mn0);
                s[mf][j][1] = __expf(s[mf][j][1] - mn0);
                s[mf][j][2] = __expf(s[mf][j][2] - mn1);
                s[mf][j][3] = __expf(s[mf][j][3] - mn1);
                rs0 += s[mf][j][0] + s[mf][j][1];
                rs1 += s[mf][j][2] + s[mf][j][3];
                // tf32-round and stage P (D-frag layout) into Qs
                *(float2*)&Qs[rr0 * KLD + j * 8 + 2 * tig] =
                    make_float2(TF32(s[mf][j][0]), TF32(s[mf][j][1]));
                *(float2*)&Qs[rr1 * KLD + j * 8 + 2 * tig] =
                    make_float2(TF32(s[mf][j][2]), TF32(s[mf][j][3]));
            }
            rs0 += __shfl_xor_sync(0xffffffffu, rs0, 1);
            rs0 += __shfl_xor_sync(0xffffffffu, rs0, 2);
            rs1 += __shfl_xor_sync(0xffffffffu, rs1, 1);
            rs1 += __shfl_xor_sync(0xffffffffu, rs1, 2);
            li[mf][0] = li[mf][0] * a0 + rs0;
            li[mf][1] = li[mf][1] * a1 + rs1;
            mi[mf][0] = mn0; mi[mf][1] = mn1;
#pragma unroll
            for (int j = 0; j < 8; j++) {
                o[mf][j][0] *= a0; o[mf][j][1] *= a0;
                o[mf][j][2] *= a1; o[mf][j][3] *= a1;
            }
        }
        __syncwarp();   // warp-private P rows are visible

        // ---- O += P @ V ; P A-frags reloaded from smem ----
#pragma unroll
        for (int kk = 0; kk < 8; kk++) {
            float pa0[4], pa1[4];
            pa0[0] = Qs[r0a * KLD + kk * 8 + tig];
            pa0[1] = Qs[r1a * KLD + kk * 8 + tig];
            pa0[2] = Qs[r0a * KLD + kk * 8 + tig + 4];
            pa0[3] = Qs[r1a * KLD + kk * 8 + tig + 4];
            pa1[0] = Qs[r0b * KLD + kk * 8 + tig];
            pa1[1] = Qs[r1b * KLD + kk * 8 + tig];
            pa1[2] = Qs[r0b * KLD + kk * 8 + tig + 4];
            pa1[3] = Qs[r1b * KLD + kk * 8 + tig + 4];
            const float* v0 = &Vst[(kk * 8 + tig) * VLD];
            const float* v1 = &Vst[(kk * 8 + tig + 4) * VLD];
#pragma unroll
            for (int j = 0; j < 8; j++) {
                const float b0 = v0[j * 8 + g];
                const float b1 = v1[j * 8 + g];
                mma8(o[0][j], pa0, b0, b1);
                mma8(o[1][j], pa1, b0, b1);
            }
        }
        __syncthreads();
    }

    // ---- normalize + write (tf32-rounded; out-proj A is pre-rounded) ----
#pragma unroll
    for (int mf = 0; mf < 2; mf++) {
        const int r0 = rb + mf * 16 + g, r1 = r0 + 8;
        const float inv0 = 1.0f / li[mf][0], inv1 = 1.0f / li[mf][1];
        float* dst0 = g_ao + ((size_t)b * SS + (q0 + r0)) * DD + h * HD;
        float* dst1 = g_ao + ((size_t)b * SS + (q0 + r1)) * DD + h * HD;
#pragma unroll
        for (int j = 0; j < 8; j++) {
            float2 w0 = make_float2(TF32(o[mf][j][0] * inv0),
                                    TF32(o[mf][j][1] * inv0));
            float2 w1 = make_float2(TF32(o[mf][j][2] * inv1),
                                    TF32(o[mf][j][3] * inv1));
            *(float2*)&dst0[j * 8 + 2 * tig] = w0;
            *(float2*)&dst1[j * 8 + 2 * tig] = w1;
        }
    }
}

// ---------------------------------------------------------------------------
extern "C" void kernel_launch(void* const* d_in, const int* in_sizes, int n_in,
                              void* d_out, int out_size)
{
    const float* x    = (const float*)d_in[0];
    const int*   mask = (const int*)  d_in[1];
    const float* Wqkv = (const float*)d_in[2];
    const float* bqkv = (const float*)d_in[3];
    const float* Wo   = (const float*)d_in[4];
    const float* bo   = (const float*)d_in[5];
    float* out = (float*)d_out;
    (void)in_sizes; (void)n_in; (void)out_size;

    cudaFuncSetAttribute(attn_k, cudaFuncAttributeMaxDynamicSharedMemorySize,
                         ATTN_SMEM);
    cudaFuncSetAttribute(mgemm_k<0>, cudaFuncAttributeMaxDynamicSharedMemorySize,
                         GSMEM);
    cudaFuncSetAttribute(mgemm_k<1>, cudaFuncAttributeMaxDynamicSharedMemorySize,
                         GSMEM);

    // 0) single fused pre-pass (tf32 rounding + mask packing)
    prepass_k<<<(PRE_TOT + 255) / 256, 256>>>(
        (const float4*)x, (const float4*)Wqkv, (const float4*)Wo, mask);

    // 1) QKV projection -> q/k/v (tf32-rounded, q pre-scaled)
    {
        dim3 grid(3 * DD / 128, (BB * SS) / 128);
        mgemm_k<0><<<grid, 128, GSMEM>>>(bqkv, nullptr, 3 * DD, DD);
    }

    // 2) Flash attention -> g_ao
    attn_k<<<dim3(SS / 128, HH, BB), 128, ATTN_SMEM>>>();

    // 3) Output projection -> d_out
    {
        dim3 grid(DD / 128, (BB * SS) / 128);
        mgemm_k<1><<<grid, 128, GSMEM>>>(bo, out, DD, DD);
    }
}

// round 12
// speedup vs baseline: 1.3872x; 1.3121x over previous
#include <cuda_runtime.h>
#include <cuda_fp16.h>
#include <mma.h>
#include <cstdint>

using namespace nvcuda;

#define BB 4
#define SS 1024
#define DD 1024
#define HH 16
#define HD 64
#define KK 1024

// Scratch (__device__ globals — allocation-free rule)
static __device__ float  g_q[BB * HH * SS * HD];
static __device__ float  g_k[BB * HH * SS * HD];
static __device__ float  g_v[BB * HH * SS * HD];
static __device__ __half g_xh[BB * SS * DD];        // fp16 x [M][K]
static __device__ __half g_wqkvh[3 * DD * DD];      // fp16 Wqkv^T [N][K]
static __device__ __half g_woh[DD * DD];            // fp16 Wo^T   [N][K]
static __device__ __half g_aoh[BB * SS * DD];       // fp16 attn out [M][K]
static __device__ uint32_t g_mb[BB * SS * (SS / 32)];

__device__ __forceinline__ void cpa16(void* dst, const void* src) {
    unsigned d = (unsigned)__cvta_generic_to_shared(dst);
    asm volatile("cp.async.cg.shared.global [%0], [%1], 16;\n" :: "r"(d), "l"(src));
}
#define CP_COMMIT() asm volatile("cp.async.commit_group;\n" ::)
#define CP_WAIT(N)  asm volatile("cp.async.wait_group %0;\n" :: "n"(N))

#define TF32(x) wmma::__float_to_tf32(x)

// fp16 m16n8k16 mma (A row-major, B col-major), fp32 accum, in place
__device__ __forceinline__ void mma16(float* d, const uint32_t* a,
                                      uint32_t b0, uint32_t b1) {
    asm volatile(
        "mma.sync.aligned.m16n8k16.row.col.f32.f16.f16.f32 "
        "{%0,%1,%2,%3}, {%4,%5,%6,%7}, {%8,%9}, {%0,%1,%2,%3};"
        : "+f"(d[0]), "+f"(d[1]), "+f"(d[2]), "+f"(d[3])
        : "r"(a[0]), "r"(a[1]), "r"(a[2]), "r"(a[3]), "r"(b0), "r"(b1));
}

// tf32 m16n8k8 mma (attention, unchanged)
__device__ __forceinline__ void mma8(float* d, const float* a,
                                     float b0, float b1) {
    asm volatile(
        "mma.sync.aligned.m16n8k8.row.col.f32.tf32.tf32.f32 "
        "{%0,%1,%2,%3}, {%4,%5,%6,%7}, {%8,%9}, {%0,%1,%2,%3};"
        : "+f"(d[0]), "+f"(d[1]), "+f"(d[2]), "+f"(d[3])
        : "r"(__float_as_uint(a[0])), "r"(__float_as_uint(a[1])),
          "r"(__float_as_uint(a[2])), "r"(__float_as_uint(a[3])),
          "r"(__float_as_uint(b0)), "r"(__float_as_uint(b1)));
}

// ---------------------------------------------------------------------------
// Pre-passes.
// prepass_k: x -> g_xh (fp16), mask -> g_mb, one launch.
// tr_h: W [K][C] fp32 -> Wt [C][K] fp16 (shared-tile transpose).
// ---------------------------------------------------------------------------
#define N4_X  (BB * SS * DD / 4)            // 1048576 float4 of x
#define N_MW  (BB * SS * (SS / 32))         // 131072 mask words
#define PRE_TOT (N4_X + N_MW)

__global__ void prepass_k(const float4* __restrict__ x,
                          const int* __restrict__ mask)
{
    int i = blockIdx.x * 256 + threadIdx.x;
    if (i < N4_X) {
        float4 v = x[i];
        __half2* dst = (__half2*)g_xh + i * 2;
        dst[0] = __floats2half2_rn(v.x, v.y);
        dst[1] = __floats2half2_rn(v.z, v.w);
    } else if (i < PRE_TOT) {
        int m = i - N4_X;
        const int4* src = (const int4*)(mask + (size_t)m * 32);
        uint32_t w = 0;
#pragma unroll
        for (int k = 0; k < 8; k++) {
            int4 v = src[k];
            w |= (v.x != 0 ? 1u : 0u) << (k * 4 + 0);
            w |= (v.y != 0 ? 1u : 0u) << (k * 4 + 1);
            w |= (v.z != 0 ? 1u : 0u) << (k * 4 + 2);
            w |= (v.w != 0 ? 1u : 0u) << (k * 4 + 3);
        }
        g_mb[m] = w;
    }
}

// src[KK][C] -> dst[C][KK] fp16. grid (C/32, KK/32), block (32,8).
__global__ void tr_h(const float* __restrict__ src, int which, int C) {
    __shared__ float t[32][33];
    __half* dst = (which == 0) ? g_wqkvh : g_woh;
    const int bx = blockIdx.x * 32;   // C dim
    const int by = blockIdx.y * 32;   // K dim
#pragma unroll
    for (int i = 0; i < 32; i += 8)
        t[threadIdx.y + i][threadIdx.x] =
            src[(size_t)(by + threadIdx.y + i) * C + bx + threadIdx.x];
    __syncthreads();
#pragma unroll
    for (int i = 0; i < 32; i += 8)
        dst[(size_t)(bx + threadIdx.y + i) * KK + by + threadIdx.x] =
            __float2half_rn(t[threadIdx.x][threadIdx.y + i]);
}

// ---------------------------------------------------------------------------
// fp16 mma.sync GEMM. CTA 128x128, BK=32 halfs (2 k16 steps), 128 thr
// (4 warps, warp tile 64x64). 3-stage cp.async ring, 1 barrier/slab.
// smem per stage: A[128][40] + B[128][40] halfs = 20480 B (80B row stride,
// banks 20*row+tig conflict-free). A = [M][K] fp16, B = [N][K] fp16 (transposed).
// MODE 0: A=g_xh,  B=g_wqkvh -> scatter q(*0.125, tf32)/k/v (fp32)
// MODE 1: A=g_aoh, B=g_woh   -> C = acc + bias (fp32 final out)
// ---------------------------------------------------------------------------
#define HSTG 10240                 // halfs per stage
#define GSMEM (3 * HSTG * 2)       // bytes

template <int MODE>
__global__ void __launch_bounds__(128, 2) hgemm_k(
    const float* __restrict__ bias, float* __restrict__ C, int N)
{
    extern __shared__ __half hsm[];

    const int tid = threadIdx.x, lane = tid & 31, warp = tid >> 5;
    const int g = lane >> 2, tig = lane & 3;
    const int wm = (warp >> 1) * 64, wn = (warp & 1) * 64;
    const int m0 = blockIdx.y * 128, n0 = blockIdx.x * 128;

    const __half* Ap = (MODE == 0) ? (const __half*)g_xh : (const __half*)g_aoh;
    const __half* Bp = (MODE == 0) ? (const __half*)g_wqkvh : (const __half*)g_woh;

    auto issue = [&](int st, int k0) {
        __half* As = hsm + st * HSTG;
        __half* Bs = As + 5120;
#pragma unroll
        for (int v = 0; v < 4; v++) {
            int id = tid + v * 128;          // 0..511
            int row = id >> 2, c = id & 3;   // row 0..127, 16B chunk
            cpa16(&As[row * 40 + c * 8],
                  Ap + (size_t)(m0 + row) * KK + k0 + c * 8);
            cpa16(&Bs[row * 40 + c * 8],
                  Bp + (size_t)(n0 + row) * KK + k0 + c * 8);
        }
    };

    float d[4][8][4];
#pragma unroll
    for (int mf = 0; mf < 4; mf++)
#pragma unroll
        for (int nf = 0; nf < 8; nf++)
#pragma unroll
            for (int c = 0; c < 4; c++) d[mf][nf][c] = 0.0f;

    issue(0, 0);  CP_COMMIT();
    issue(1, 32); CP_COMMIT();

    const int NI = KK / 32;
    for (int i = 0; i < NI; i++) {
        const int st = i % 3;
        CP_WAIT(1);
        __syncthreads();
        if (i + 2 < NI) issue((i + 2) % 3, (i + 2) * 32);
        CP_COMMIT();

        const __half* As = hsm + st * HSTG;
        const __half* Bs = As + 5120;

        uint32_t af[2][4][4], bf[2][8][2];
        auto ldA = [&](int buf, int kk) {
#pragma unroll
            for (int mf = 0; mf < 4; mf++) {
                const __half* p0 = &As[(wm + mf * 16 + g) * 40 + kk * 16 + 2 * tig];
                const __half* p1 = p0 + 8 * 40;   // row +8
                af[buf][mf][0] = *(const uint32_t*)p0;
                af[buf][mf][1] = *(const uint32_t*)p1;
                af[buf][mf][2] = *(const uint32_t*)(p0 + 8);
                af[buf][mf][3] = *(const uint32_t*)(p1 + 8);
            }
        };
        auto ldB = [&](int buf, int kk) {
#pragma unroll
            for (int nf = 0; nf < 8; nf++) {
                const __half* p = &Bs[(wn + nf * 8 + g) * 40 + kk * 16 + 2 * tig];
                bf[buf][nf][0] = *(const uint32_t*)p;
                bf[buf][nf][1] = *(const uint32_t*)(p + 8);
            }
        };
        ldA(0, 0); ldB(0, 0);
#pragma unroll
        for (int kk = 0; kk < 2; kk++) {
            const int cur = kk & 1;
            if (kk < 1) { ldA(cur ^ 1, kk + 1); ldB(cur ^ 1, kk + 1); }
#pragma unroll
            for (int mf = 0; mf < 4; mf++)
#pragma unroll
                for (int nf = 0; nf < 8; nf++)
                    mma16(d[mf][nf], af[cur][mf], bf[cur][nf][0], bf[cur][nf][1]);
        }
    }

    // ---- direct epilogue (D-frag rows g,g+8; cols 2tig,2tig+1) ----
#pragma unroll
    for (int mf = 0; mf < 4; mf++) {
        const int m = m0 + wm + mf * 16 + g;
        const int bb = m >> 10, srow = m & 1023;
#pragma unroll
        for (int nf = 0; nf < 8; nf++) {
            const int col0 = n0 + wn + nf * 8 + 2 * tig;
            const float b0 = bias[col0], b1 = bias[col0 + 1];
            float v0 = d[mf][nf][0] + b0, v1 = d[mf][nf][1] + b1;
            float v2 = d[mf][nf][2] + b0, v3 = d[mf][nf][3] + b1;

            if (MODE == 0) {
                const int h = col0 / 192;
                const int rr = col0 - h * 192;
                const int seg = rr >> 6;
                const int db = rr & 63;
                const size_t idx =
                    (((size_t)(bb * HH + h)) * SS + srow) * HD + db;
                float* dst = (seg == 0) ? g_q : (seg == 1) ? g_k : g_v;
                const float sc = (seg == 0) ? 0.125f : 1.0f;
                float2 w0 = make_float2(TF32(v0 * sc), TF32(v1 * sc));
                float2 w1 = make_float2(TF32(v2 * sc), TF32(v3 * sc));
                *(float2*)&dst[idx]          = w0;
                *(float2*)&dst[idx + 8 * HD] = w1;
            } else {
                float* dst = C + (size_t)m * N + col0;
                *(float2*)dst           = make_float2(v0, v1);
                *(float2*)(dst + 8 * N) = make_float2(v2, v3);
            }
        }
    }
}

// ---------------------------------------------------------------------------
// Flash attention FA2, mma.sync tf32 (unchanged from round 11) — except the
// final epilogue writes fp16 g_aoh for the fp16 out-projection.
// smem floats: Qs[128][68]=8704 | Ks[2][64][68]=8704 | Vs[2][64][72]=9216
// ---------------------------------------------------------------------------
#define KLD 68
#define VLD 72
#define NT (SS / 64)
#define ATTN_SMEM (26624 * 4)

__global__ void __launch_bounds__(128, 2) attn_k(void)
{
    extern __shared__ float sm[];
    float* Qs = sm;           // q staging, then reused as P buffer
    float* Ks = sm + 8704;    // stage stride 4352
    float* Vs = sm + 17408;   // stage stride 4608

    const int tid = threadIdx.x, lane = tid & 31, warp = tid >> 5;
    const int g = lane >> 2, tig = lane & 3;
    const int q0 = blockIdx.x * 128;
    const int h = blockIdx.y, b = blockIdx.z;
    const size_t bh = (size_t)(b * HH + h);
    const float* qb = g_q + bh * SS * HD;
    const float* kb = g_k + bh * SS * HD;
    const float* vb = g_v + bh * SS * HD;

#pragma unroll
    for (int j = 0; j < 16; j++) {
        int idx = tid + j * 128;
        int r = idx >> 4, c4 = idx & 15;
        *(float4*)&Qs[r * KLD + c4 * 4] =
            *(const float4*)(qb + (size_t)(q0 + r) * HD + c4 * 4);
    }
#pragma unroll
    for (int j = 0; j < 8; j++) {
        int idx = tid + j * 128;
        int r = idx >> 4, c4 = idx & 15;
        cpa16(&Ks[r * KLD + c4 * 4], kb + (size_t)r * HD + c4 * 4);
        cpa16(&Vs[r * VLD + c4 * 4], vb + (size_t)r * HD + c4 * 4);
    }
    CP_COMMIT();
    __syncthreads();

    const int rb = 32 * warp;
    const int r0a = rb + g,      r1a = rb + g + 8;
    const int r0b = rb + 16 + g, r1b = rb + 16 + g + 8;

    float qf[2][8][4];
#pragma unroll
    for (int mf = 0; mf < 2; mf++) {
        const int r0 = rb + mf * 16 + g, r1 = r0 + 8;
#pragma unroll
        for (int kk = 0; kk < 8; kk++) {
            qf[mf][kk][0] = Qs[r0 * KLD + kk * 8 + tig];
            qf[mf][kk][1] = Qs[r1 * KLD + kk * 8 + tig];
            qf[mf][kk][2] = Qs[r0 * KLD + kk * 8 + tig + 4];
            qf[mf][kk][3] = Qs[r1 * KLD + kk * 8 + tig + 4];
        }
    }
    __syncthreads();   // Qs is now the P buffer

    float o[2][8][4];
#pragma unroll
    for (int mf = 0; mf < 2; mf++)
#pragma unroll
        for (int j = 0; j < 8; j++)
#pragma unroll
            for (int c = 0; c < 4; c++) o[mf][j][c] = 0.0f;
    float mi[2][2], li[2][2];
#pragma unroll
    for (int mf = 0; mf < 2; mf++) {
        mi[mf][0] = mi[mf][1] = -1e30f;
        li[mf][0] = li[mf][1] = 0.0f;
    }

    const uint32_t* mb0 = g_mb + ((size_t)b * SS + (q0 + r0a)) * 32;
    const uint32_t* mb1 = g_mb + ((size_t)b * SS + (q0 + r1a)) * 32;
    const uint32_t* mb2 = g_mb + ((size_t)b * SS + (q0 + r0b)) * 32;
    const uint32_t* mb3 = g_mb + ((size_t)b * SS + (q0 + r1b)) * 32;

    for (int t = 0; t < NT; t++) {
        const int st = t & 1;
        if (t + 1 < NT) {
            const float* kb2 = kb + (size_t)(t + 1) * 64 * HD;
            const float* vb2 = vb + (size_t)(t + 1) * 64 * HD;
            float* Kd = Ks + (st ^ 1) * 4352;
            float* Vd = Vs + (st ^ 1) * 4608;
#pragma unroll
            for (int j = 0; j < 8; j++) {
                int idx = tid + j * 128;
                int rr = idx >> 4, c4 = idx & 15;
                cpa16(&Kd[rr * KLD + c4 * 4], kb2 + (size_t)rr * HD + c4 * 4);
                cpa16(&Vd[rr * VLD + c4 * 4], vb2 + (size_t)rr * HD + c4 * 4);
            }
        }
        CP_COMMIT();

        uint2 mw[4];
        mw[0] = *(const uint2*)(mb0 + t * 2);
        mw[1] = *(const uint2*)(mb1 + t * 2);
        mw[2] = *(const uint2*)(mb2 + t * 2);
        mw[3] = *(const uint2*)(mb3 + t * 2);

        CP_WAIT(1);
        __syncthreads();

        const float* Kst = Ks + st * 4352;
        const float* Vst = Vs + st * 4608;

        float s[2][8][4];
#pragma unroll
        for (int j = 0; j < 8; j++) {
            s[0][j][0] = s[0][j][1] = s[0][j][2] = s[0][j][3] = 0.0f;
            s[1][j][0] = s[1][j][1] = s[1][j][2] = s[1][j][3] = 0.0f;
            const float* krow = &Kst[(j * 8 + g) * KLD];
#pragma unroll
            for (int kk = 0; kk < 8; kk++) {
                const float b0 = krow[kk * 8 + tig];
                const float b1 = krow[kk * 8 + tig + 4];
                mma8(s[0][j], qf[0][kk], b0, b1);
                mma8(s[1][j], qf[1][kk], b0, b1);
            }
        }

#pragma unroll
        for (int mf = 0; mf < 2; mf++) {
#pragma unroll
            for (int j = 0; j < 8; j++) {
                const int bit = (j * 8 + 2 * tig) & 31;
                const uint32_t wa = (j < 4) ? mw[mf * 2].x     : mw[mf * 2].y;
                const uint32_t wb = (j < 4) ? mw[mf * 2 + 1].x : mw[mf * 2 + 1].y;
                if (!((wa >> bit) & 1))       s[mf][j][0] = -1e20f;
                if (!((wa >> (bit + 1)) & 1)) s[mf][j][1] = -1e20f;
                if (!((wb >> bit) & 1))       s[mf][j][2] = -1e20f;
                if (!((wb >> (bit + 1)) & 1)) s[mf][j][3] = -1e20f;
            }
        }

#pragma unroll
        for (int mf = 0; mf < 2; mf++) {
            float mx0 = s[mf][0][0], mx1 = s[mf][0][2];
#pragma unroll
            for (int j = 0; j < 8; j++) {
                mx0 = fmaxf(mx0, fmaxf(s[mf][j][0], s[mf][j][1]));
                mx1 = fmaxf(mx1, fmaxf(s[mf][j][2], s[mf][j][3]));
            }
            mx0 = fmaxf(mx0, __shfl_xor_sync(0xffffffffu, mx0, 1));
            mx0 = fmaxf(mx0, __shfl_xor_sync(0xffffffffu, mx0, 2));
            mx1 = fmaxf(mx1, __shfl_xor_sync(0xffffffffu, mx1, 1));
            mx1 = fmaxf(mx1, __shfl_xor_sync(0xffffffffu, mx1, 2));
            const float mn0 = fmaxf(mi[mf][0], mx0);
            const float mn1 = fmaxf(mi[mf][1], mx1);
            const float a0 = __expf(mi[mf][0] - mn0);
            const float a1 = __expf(mi[mf][1] - mn1);
            float rs0 = 0.0f, rs1 = 0.0f;
            const int rr0 = rb + mf * 16 + g, rr1 = rr0 + 8;
#pragma unroll
            for (int j = 0; j < 8; j++) {
                s[mf][j][0] = __expf(s[mf][j][0] - mn0);
                s[mf][j][1] = __expf(s[mf][j][1] - mn0);
                s[mf][j][2] = __expf(s[mf][j][2] - mn1);
                s[mf][j][3] = __expf(s[mf][j][3] - mn1);
                rs0 += s[mf][j][0] + s[mf][j][1];
                rs1 += s[mf][j][2] + s[mf][j][3];
                *(float2*)&Qs[rr0 * KLD + j * 8 + 2 * tig] =
                    make_float2(TF32(s[mf][j][0]), TF32(s[mf][j][1]));
                *(float2*)&Qs[rr1 * KLD + j * 8 + 2 * tig] =
                    make_float2(TF32(s[mf][j][2]), TF32(s[mf][j][3]));
            }
            rs0 += __shfl_xor_sync(0xffffffffu, rs0, 1);
            rs0 += __shfl_xor_sync(0xffffffffu, rs0, 2);
            rs1 += __shfl_xor_sync(0xffffffffu, rs1, 1);
            rs1 += __shfl_xor_sync(0xffffffffu, rs1, 2);
            li[mf][0] = li[mf][0] * a0 + rs0;
            li[mf][1] = li[mf][1] * a1 + rs1;
            mi[mf][0] = mn0; mi[mf][1] = mn1;
#pragma unroll
            for (int j = 0; j < 8; j++) {
                o[mf][j][0] *= a0; o[mf][j][1] *= a0;
                o[mf][j][2] *= a1; o[mf][j][3] *= a1;
            }
        }
        __syncwarp();

#pragma unroll
        for (int kk = 0; kk < 8; kk++) {
            float pa0[4], pa1[4];
            pa0[0] = Qs[r0a * KLD + kk * 8 + tig];
            pa0[1] = Qs[r1a * KLD + kk * 8 + tig];
            pa0[2] = Qs[r0a * KLD + kk * 8 + tig + 4];
            pa0[3] = Qs[r1a * KLD + kk * 8 + tig + 4];
            pa1[0] = Qs[r0b * KLD + kk * 8 + tig];
            pa1[1] = Qs[r1b * KLD + kk * 8 + tig];
            pa1[2] = Qs[r0b * KLD + kk * 8 + tig + 4];
            pa1[3] = Qs[r1b * KLD + kk * 8 + tig + 4];
            const float* v0 = &Vst[(kk * 8 + tig) * VLD];
            const float* v1 = &Vst[(kk * 8 + tig + 4) * VLD];
#pragma unroll
            for (int j = 0; j < 8; j++) {
                const float b0 = v0[j * 8 + g];
                const float b1 = v1[j * 8 + g];
                mma8(o[0][j], pa0, b0, b1);
                mma8(o[1][j], pa1, b0, b1);
            }
        }
        __syncthreads();
    }

    // ---- normalize + write fp16 g_aoh (feeds the fp16 out-proj) ----
#pragma unroll
    for (int mf = 0; mf < 2; mf++) {
        const int r0 = rb + mf * 16 + g, r1 = r0 + 8;
        const float inv0 = 1.0f / li[mf][0], inv1 = 1.0f / li[mf][1];
        __half* dst0 = g_aoh + ((size_t)b * SS + (q0 + r0)) * DD + h * HD;
        __half* dst1 = g_aoh + ((size_t)b * SS + (q0 + r1)) * DD + h * HD;
#pragma unroll
        for (int j = 0; j < 8; j++) {
            *(__half2*)&dst0[j * 8 + 2 * tig] =
                __floats2half2_rn(o[mf][j][0] * inv0, o[mf][j][1] * inv0);
            *(__half2*)&dst1[j * 8 + 2 * tig] =
                __floats2half2_rn(o[mf][j][2] * inv1, o[mf][j][3] * inv1);
        }
    }
}

// ---------------------------------------------------------------------------
extern "C" void kernel_launch(void* const* d_in, const int* in_sizes, int n_in,
                              void* d_out, int out_size)
{
    const float* x    = (const float*)d_in[0];
    const int*   mask = (const int*)  d_in[1];
    const float* Wqkv = (const float*)d_in[2];
    const float* bqkv = (const float*)d_in[3];
    const float* Wo   = (const float*)d_in[4];
    const float* bo   = (const float*)d_in[5];
    float* out = (float*)d_out;
    (void)in_sizes; (void)n_in; (void)out_size;

    cudaFuncSetAttribute(attn_k, cudaFuncAttributeMaxDynamicSharedMemorySize,
                         ATTN_SMEM);
    cudaFuncSetAttribute(hgemm_k<0>, cudaFuncAttributeMaxDynamicSharedMemorySize,
                         GSMEM);
    cudaFuncSetAttribute(hgemm_k<1>, cudaFuncAttributeMaxDynamicSharedMemorySize,
                         GSMEM);

    // 0) pre-passes: x->fp16 + mask pack (one launch), weight transposes
    prepass_k<<<(PRE_TOT + 255) / 256, 256>>>((const float4*)x, mask);
    tr_h<<<dim3(3 * DD / 32, KK / 32), dim3(32, 8)>>>(Wqkv, 0, 3 * DD);
    tr_h<<<dim3(DD / 32, KK / 32), dim3(32, 8)>>>(Wo, 1, DD);

    // 1) QKV projection (fp16 mma) -> q/k/v (fp32, tf32-rounded)
    {
        dim3 grid(3 * DD / 128, (BB * SS) / 128);
        hgemm_k<0><<<grid, 128, GSMEM>>>(bqkv, nullptr, 3 * DD);
    }

    // 2) Flash attention (tf32 mma) -> g_aoh (fp16)
    attn_k<<<dim3(SS / 128, HH, BB), 128, ATTN_SMEM>>>();

    // 3) Output projection (fp16 mma) -> d_out (fp32)
    {
        dim3 grid(DD / 128, (BB * SS) / 128);
        hgemm_k<1><<<grid, 128, GSMEM>>>(bo, out, DD);
    }
}

// round 13
// speedup vs baseline: 1.6963x; 1.2229x over previous
#include <cuda_runtime.h>
#include <cuda_fp16.h>
#include <mma.h>
#include <cstdint>

#define BB 4
#define SS 1024
#define DD 1024
#define HH 16
#define HD 64
#define KK 1024

// Scratch (__device__ globals — allocation-free rule)
static __device__ __half g_qh[BB * HH * SS * HD];   // fp16 q [bh][S][hd], pre-scaled
static __device__ __half g_kh[BB * HH * SS * HD];   // fp16 k [bh][S][hd]
static __device__ __half g_vth[BB * HH * HD * SS];  // fp16 v TRANSPOSED [bh][hd][S]
static __device__ __half g_xh[BB * SS * DD];        // fp16 x [M][K]
static __device__ __half g_wqkvh[3 * DD * DD];      // fp16 Wqkv^T [N][K]
static __device__ __half g_woh[DD * DD];            // fp16 Wo^T   [N][K]
static __device__ __half g_aoh[BB * SS * DD];       // fp16 attn out [M][K]
static __device__ uint32_t g_mb[BB * SS * (SS / 32)];

__device__ __forceinline__ void cpa16(void* dst, const void* src) {
    unsigned d = (unsigned)__cvta_generic_to_shared(dst);
    asm volatile("cp.async.cg.shared.global [%0], [%1], 16;\n" :: "r"(d), "l"(src));
}
#define CP_COMMIT() asm volatile("cp.async.commit_group;\n" ::)
#define CP_WAIT(N)  asm volatile("cp.async.wait_group %0;\n" :: "n"(N))

// fp16 m16n8k16 mma (A row-major, B col-major), fp32 accum, in place
__device__ __forceinline__ void mma16(float* d, const uint32_t* a,
                                      uint32_t b0, uint32_t b1) {
    asm volatile(
        "mma.sync.aligned.m16n8k16.row.col.f32.f16.f16.f32 "
        "{%0,%1,%2,%3}, {%4,%5,%6,%7}, {%8,%9}, {%0,%1,%2,%3};"
        : "+f"(d[0]), "+f"(d[1]), "+f"(d[2]), "+f"(d[3])
        : "r"(a[0]), "r"(a[1]), "r"(a[2]), "r"(a[3]), "r"(b0), "r"(b1));
}

// ---------------------------------------------------------------------------
// Pre-passes: x->fp16 + mask pack (one launch); weight transposes to fp16.
// ---------------------------------------------------------------------------
#define N4_X  (BB * SS * DD / 4)
#define N_MW  (BB * SS * (SS / 32))
#define PRE_TOT (N4_X + N_MW)

__global__ void prepass_k(const float4* __restrict__ x,
                          const int* __restrict__ mask)
{
    int i = blockIdx.x * 256 + threadIdx.x;
    if (i < N4_X) {
        float4 v = x[i];
        __half2* dst = (__half2*)g_xh + i * 2;
        dst[0] = __floats2half2_rn(v.x, v.y);
        dst[1] = __floats2half2_rn(v.z, v.w);
    } else if (i < PRE_TOT) {
        int m = i - N4_X;
        const int4* src = (const int4*)(mask + (size_t)m * 32);
        uint32_t w = 0;
#pragma unroll
        for (int k = 0; k < 8; k++) {
            int4 v = src[k];
            w |= (v.x != 0 ? 1u : 0u) << (k * 4 + 0);
            w |= (v.y != 0 ? 1u : 0u) << (k * 4 + 1);
            w |= (v.z != 0 ? 1u : 0u) << (k * 4 + 2);
            w |= (v.w != 0 ? 1u : 0u) << (k * 4 + 3);
        }
        g_mb[m] = w;
    }
}

// src[KK][C] -> dst[C][KK] fp16. grid (C/32, KK/32), block (32,8).
__global__ void tr_h(const float* __restrict__ src, int which, int C) {
    __shared__ float t[32][33];
    __half* dst = (which == 0) ? g_wqkvh : g_woh;
    const int bx = blockIdx.x * 32;
    const int by = blockIdx.y * 32;
#pragma unroll
    for (int i = 0; i < 32; i += 8)
        t[threadIdx.y + i][threadIdx.x] =
            src[(size_t)(by + threadIdx.y + i) * C + bx + threadIdx.x];
    __syncthreads();
#pragma unroll
    for (int i = 0; i < 32; i += 8)
        dst[(size_t)(bx + threadIdx.y + i) * KK + by + threadIdx.x] =
            __float2half_rn(t[threadIdx.x][threadIdx.y + i]);
}

// ---------------------------------------------------------------------------
// fp16 mma.sync GEMM (round-12). CTA 128x128, BK=32 halfs, 128 thr, warp
// tile 64x64, 3-stage cp.async ring. MODE 0 epilogue now writes fp16 q/k
// and TRANSPOSED fp16 v. MODE 1: C = acc + bias (fp32 final out).
// ---------------------------------------------------------------------------
#define HSTG 10240
#define GSMEM (3 * HSTG * 2)

template <int MODE>
__global__ void __launch_bounds__(128, 2) hgemm_k(
    const float* __restrict__ bias, float* __restrict__ C, int N)
{
    extern __shared__ __half hsm[];

    const int tid = threadIdx.x, lane = tid & 31, warp = tid >> 5;
    const int g = lane >> 2, tig = lane & 3;
    const int wm = (warp >> 1) * 64, wn = (warp & 1) * 64;
    const int m0 = blockIdx.y * 128, n0 = blockIdx.x * 128;

    const __half* Ap = (MODE == 0) ? (const __half*)g_xh : (const __half*)g_aoh;
    const __half* Bp = (MODE == 0) ? (const __half*)g_wqkvh : (const __half*)g_woh;

    auto issue = [&](int st, int k0) {
        __half* As = hsm + st * HSTG;
        __half* Bs = As + 5120;
#pragma unroll
        for (int v = 0; v < 4; v++) {
            int id = tid + v * 128;
            int row = id >> 2, c = id & 3;
            cpa16(&As[row * 40 + c * 8],
                  Ap + (size_t)(m0 + row) * KK + k0 + c * 8);
            cpa16(&Bs[row * 40 + c * 8],
                  Bp + (size_t)(n0 + row) * KK + k0 + c * 8);
        }
    };

    float d[4][8][4];
#pragma unroll
    for (int mf = 0; mf < 4; mf++)
#pragma unroll
        for (int nf = 0; nf < 8; nf++)
#pragma unroll
            for (int c = 0; c < 4; c++) d[mf][nf][c] = 0.0f;

    issue(0, 0);  CP_COMMIT();
    issue(1, 32); CP_COMMIT();

    const int NI = KK / 32;
    for (int i = 0; i < NI; i++) {
        const int st = i % 3;
        CP_WAIT(1);
        __syncthreads();
        if (i + 2 < NI) issue((i + 2) % 3, (i + 2) * 32);
        CP_COMMIT();

        const __half* As = hsm + st * HSTG;
        const __half* Bs = As + 5120;

        uint32_t af[2][4][4], bf[2][8][2];
        auto ldA = [&](int buf, int kk) {
#pragma unroll
            for (int mf = 0; mf < 4; mf++) {
                const __half* p0 = &As[(wm + mf * 16 + g) * 40 + kk * 16 + 2 * tig];
                const __half* p1 = p0 + 8 * 40;
                af[buf][mf][0] = *(const uint32_t*)p0;
                af[buf][mf][1] = *(const uint32_t*)p1;
                af[buf][mf][2] = *(const uint32_t*)(p0 + 8);
                af[buf][mf][3] = *(const uint32_t*)(p1 + 8);
            }
        };
        auto ldB = [&](int buf, int kk) {
#pragma unroll
            for (int nf = 0; nf < 8; nf++) {
                const __half* p = &Bs[(wn + nf * 8 + g) * 40 + kk * 16 + 2 * tig];
                bf[buf][nf][0] = *(const uint32_t*)p;
                bf[buf][nf][1] = *(const uint32_t*)(p + 8);
            }
        };
        ldA(0, 0); ldB(0, 0);
#pragma unroll
        for (int kk = 0; kk < 2; kk++) {
            const int cur = kk & 1;
            if (kk < 1) { ldA(cur ^ 1, kk + 1); ldB(cur ^ 1, kk + 1); }
#pragma unroll
            for (int mf = 0; mf < 4; mf++)
#pragma unroll
                for (int nf = 0; nf < 8; nf++)
                    mma16(d[mf][nf], af[cur][mf], bf[cur][nf][0], bf[cur][nf][1]);
        }
    }

    // ---- epilogue ----
#pragma unroll
    for (int mf = 0; mf < 4; mf++) {
        const int m = m0 + wm + mf * 16 + g;
        const int bb = m >> 10, srow = m & 1023;
#pragma unroll
        for (int nf = 0; nf < 8; nf++) {
            const int col0 = n0 + wn + nf * 8 + 2 * tig;
            const float b0 = bias[col0], b1 = bias[col0 + 1];
            float v0 = d[mf][nf][0] + b0, v1 = d[mf][nf][1] + b1;
            float v2 = d[mf][nf][2] + b0, v3 = d[mf][nf][3] + b1;

            if (MODE == 0) {
                const int h = col0 / 192;
                const int rr = col0 - h * 192;
                const int seg = rr >> 6;
                const int db = rr & 63;
                const size_t bhb = (size_t)(bb * HH + h);
                if (seg == 2) {
                    // transposed v: [bh][hd][S]
                    __half* vd = g_vth + (bhb * HD + db) * SS;
                    vd[srow]          = __float2half_rn(v0);
                    vd[SS + srow]     = __float2half_rn(v1);
                    vd[srow + 8]      = __float2half_rn(v2);
                    vd[SS + srow + 8] = __float2half_rn(v3);
                } else {
                    __half* dst = (seg == 0) ? g_qh : g_kh;
                    const float sc = (seg == 0) ? 0.125f : 1.0f;
                    const size_t idx = (bhb * SS + srow) * HD + db;
                    *(__half2*)&dst[idx] =
                        __floats2half2_rn(v0 * sc, v1 * sc);
                    *(__half2*)&dst[idx + 8 * HD] =
                        __floats2half2_rn(v2 * sc, v3 * sc);
                }
            } else {
                float* dst = C + (size_t)m * N + col0;
                *(float2*)dst           = make_float2(v0, v1);
                *(float2*)(dst + 8 * N) = make_float2(v2, v3);
            }
        }
    }
}

// ---------------------------------------------------------------------------
// Flash attention FA2, full fp16 mma (m16n8k16), fp32 softmax/accum.
// 128 thr (4 warps), q-block 128, warp q-tile 32 (2 m-frags). KV tile 64,
// double-buffered cp.async. P staged fp16 in the dead Q buffer.
// smem halves: Qs[128][72]=9216 | Ks[2][64][72]=9216 | Vt[2][64][72]=9216
// (Vt rows are head-dims, cols are kv positions). Total 55296 B.
// ---------------------------------------------------------------------------
#define LDH 72
#define NT (SS / 64)
#define ATTN_SMEM (27648 * 2)

__global__ void __launch_bounds__(128, 2) attn_k(void)
{
    extern __shared__ __half hsm[];
    __half* Qs = hsm;            // q staging, then P buffer
    __half* Ks = hsm + 9216;     // stage stride 4608 halves
    __half* Vs = hsm + 18432;    // transposed V tiles, stage stride 4608

    const int tid = threadIdx.x, lane = tid & 31, warp = tid >> 5;
    const int g = lane >> 2, tig = lane & 3;
    const int q0 = blockIdx.x * 128;
    const int h = blockIdx.y, b = blockIdx.z;
    const size_t bh = (size_t)(b * HH + h);
    const __half* qb  = g_qh  + bh * SS * HD;
    const __half* kb  = g_kh  + bh * SS * HD;
    const __half* vtb = g_vth + bh * HD * SS;

    // Q tile (128x64 halves) + KV tile 0, all one cp.async group
#pragma unroll
    for (int j = 0; j < 8; j++) {
        int idx = tid + j * 128;
        int r = idx >> 3, c = idx & 7;
        cpa16(&Qs[r * LDH + c * 8], qb + (size_t)(q0 + r) * HD + c * 8);
    }
#pragma unroll
    for (int j = 0; j < 4; j++) {
        int idx = tid + j * 128;
        int r = idx >> 3, c = idx & 7;
        cpa16(&Ks[r * LDH + c * 8], kb + (size_t)r * HD + c * 8);
        cpa16(&Vs[r * LDH + c * 8], vtb + (size_t)r * SS + c * 8);
    }
    CP_COMMIT();
    CP_WAIT(0);
    __syncthreads();

    const int rb = 32 * warp;
    const int r0a = rb + g,      r1a = rb + g + 8;
    const int r0b = rb + 16 + g, r1b = rb + 16 + g + 8;

    // Q A-frags (m16n8k16): 4 k-steps of 16
    uint32_t qf[2][4][4];
#pragma unroll
    for (int mf = 0; mf < 2; mf++) {
        const int r0 = rb + mf * 16 + g, r1 = r0 + 8;
#pragma unroll
        for (int kk = 0; kk < 4; kk++) {
            const __half* p0 = &Qs[r0 * LDH + kk * 16 + 2 * tig];
            const __half* p1 = &Qs[r1 * LDH + kk * 16 + 2 * tig];
            qf[mf][kk][0] = *(const uint32_t*)p0;
            qf[mf][kk][1] = *(const uint32_t*)p1;
            qf[mf][kk][2] = *(const uint32_t*)(p0 + 8);
            qf[mf][kk][3] = *(const uint32_t*)(p1 + 8);
        }
    }
    __syncthreads();   // Qs is now the P buffer

    float o[2][8][4];
#pragma unroll
    for (int mf = 0; mf < 2; mf++)
#pragma unroll
        for (int j = 0; j < 8; j++)
#pragma unroll
            for (int c = 0; c < 4; c++) o[mf][j][c] = 0.0f;
    float mi[2][2], li[2][2];
#pragma unroll
    for (int mf = 0; mf < 2; mf++) {
        mi[mf][0] = mi[mf][1] = -1e30f;
        li[mf][0] = li[mf][1] = 0.0f;
    }

    const uint32_t* mb0 = g_mb + ((size_t)b * SS + (q0 + r0a)) * 32;
    const uint32_t* mb1 = g_mb + ((size_t)b * SS + (q0 + r1a)) * 32;
    const uint32_t* mb2 = g_mb + ((size_t)b * SS + (q0 + r0b)) * 32;
    const uint32_t* mb3 = g_mb + ((size_t)b * SS + (q0 + r1b)) * 32;

    for (int t = 0; t < NT; t++) {
        const int st = t & 1;
        if (t + 1 < NT) {
            const __half* kb2  = kb  + (size_t)(t + 1) * 64 * HD;
            const __half* vtb2 = vtb + (size_t)(t + 1) * 64;   // col offset
            __half* Kd = Ks + (st ^ 1) * 4608;
            __half* Vd = Vs + (st ^ 1) * 4608;
#pragma unroll
            for (int j = 0; j < 4; j++) {
                int idx = tid + j * 128;
                int r = idx >> 3, c = idx & 7;
                cpa16(&Kd[r * LDH + c * 8], kb2 + (size_t)r * HD + c * 8);
                cpa16(&Vd[r * LDH + c * 8], vtb2 + (size_t)r * SS + c * 8);
            }
        }
        CP_COMMIT();

        uint2 mw[4];
        mw[0] = *(const uint2*)(mb0 + t * 2);
        mw[1] = *(const uint2*)(mb1 + t * 2);
        mw[2] = *(const uint2*)(mb2 + t * 2);
        mw[3] = *(const uint2*)(mb3 + t * 2);

        CP_WAIT(1);
        __syncthreads();

        const __half* Kst = Ks + st * 4608;
        const __half* Vst = Vs + st * 4608;

        // ---- S = Q @ K^T (fp16 mma, fp32 accum) ----
        float s[2][8][4];
#pragma unroll
        for (int j = 0; j < 8; j++) {
            s[0][j][0] = s[0][j][1] = s[0][j][2] = s[0][j][3] = 0.0f;
            s[1][j][0] = s[1][j][1] = s[1][j][2] = s[1][j][3] = 0.0f;
            const __half* krow = &Kst[(j * 8 + g) * LDH];
#pragma unroll
            for (int kk = 0; kk < 4; kk++) {
                const uint32_t b0 = *(const uint32_t*)&krow[kk * 16 + 2 * tig];
                const uint32_t b1 = *(const uint32_t*)&krow[kk * 16 + 2 * tig + 8];
                mma16(s[0][j], qf[0][kk], b0, b1);
                mma16(s[1][j], qf[1][kk], b0, b1);
            }
        }

        // ---- bitmask ----
#pragma unroll
        for (int mf = 0; mf < 2; mf++) {
#pragma unroll
            for (int j = 0; j < 8; j++) {
                const int bit = (j * 8 + 2 * tig) & 31;
                const uint32_t wa = (j < 4) ? mw[mf * 2].x     : mw[mf * 2].y;
                const uint32_t wb = (j < 4) ? mw[mf * 2 + 1].x : mw[mf * 2 + 1].y;
                if (!((wa >> bit) & 1))       s[mf][j][0] = -1e20f;
                if (!((wa >> (bit + 1)) & 1)) s[mf][j][1] = -1e20f;
                if (!((wb >> bit) & 1))       s[mf][j][2] = -1e20f;
                if (!((wb >> (bit + 1)) & 1)) s[mf][j][3] = -1e20f;
            }
        }

        // ---- online softmax; stage fp16 P into Qs ----
#pragma unroll
        for (int mf = 0; mf < 2; mf++) {
            float mx0 = s[mf][0][0], mx1 = s[mf][0][2];
#pragma unroll
            for (int j = 0; j < 8; j++) {
                mx0 = fmaxf(mx0, fmaxf(s[mf][j][0], s[mf][j][1]));
                mx1 = fmaxf(mx1, fmaxf(s[mf][j][2], s[mf][j][3]));
            }
            mx0 = fmaxf(mx0, __shfl_xor_sync(0xffffffffu, mx0, 1));
            mx0 = fmaxf(mx0, __shfl_xor_sync(0xffffffffu, mx0, 2));
            mx1 = fmaxf(mx1, __shfl_xor_sync(0xffffffffu, mx1, 1));
            mx1 = fmaxf(mx1, __shfl_xor_sync(0xffffffffu, mx1, 2));
            const float mn0 = fmaxf(mi[mf][0], mx0);
            const float mn1 = fmaxf(mi[mf][1], mx1);
            const float a0 = __expf(mi[mf][0] - mn0);
            const float a1 = __expf(mi[mf][1] - mn1);
            float rs0 = 0.0f, rs1 = 0.0f;
            const int rr0 = rb + mf * 16 + g, rr1 = rr0 + 8;
#pragma unroll
            for (int j = 0; j < 8; j++) {
                s[mf][j][0] = __expf(s[mf][j][0] - mn0);
                s[mf][j][1] = __expf(s[mf][j][1] - mn0);
                s[mf][j][2] = __expf(s[mf][j][2] - mn1);
                s[mf][j][3] = __expf(s[mf][j][3] - mn1);
                rs0 += s[mf][j][0] + s[mf][j][1];
                rs1 += s[mf][j][2] + s[mf][j][3];
                *(__half2*)&Qs[rr0 * LDH + j * 8 + 2 * tig] =
                    __floats2half2_rn(s[mf][j][0], s[mf][j][1]);
                *(__half2*)&Qs[rr1 * LDH + j * 8 + 2 * tig] =
                    __floats2half2_rn(s[mf][j][2], s[mf][j][3]);
            }
            rs0 += __shfl_xor_sync(0xffffffffu, rs0, 1);
            rs0 += __shfl_xor_sync(0xffffffffu, rs0, 2);
            rs1 += __shfl_xor_sync(0xffffffffu, rs1, 1);
            rs1 += __shfl_xor_sync(0xffffffffu, rs1, 2);
            li[mf][0] = li[mf][0] * a0 + rs0;
            li[mf][1] = li[mf][1] * a1 + rs1;
            mi[mf][0] = mn0; mi[mf][1] = mn1;
#pragma unroll
            for (int j = 0; j < 8; j++) {
                o[mf][j][0] *= a0; o[mf][j][1] *= a0;
                o[mf][j][2] *= a1; o[mf][j][3] *= a1;
            }
        }
        __syncwarp();

        // ---- O += P @ V (fp16 mma; Vt rows = head dims) ----
#pragma unroll
        for (int kk = 0; kk < 4; kk++) {
            uint32_t pa[4], pb[4];
            {
                const __half* p0 = &Qs[r0a * LDH + kk * 16 + 2 * tig];
                const __half* p1 = &Qs[r1a * LDH + kk * 16 + 2 * tig];
                pa[0] = *(const uint32_t*)p0;
                pa[1] = *(const uint32_t*)p1;
                pa[2] = *(const uint32_t*)(p0 + 8);
                pa[3] = *(const uint32_t*)(p1 + 8);
                const __half* q0p = &Qs[r0b * LDH + kk * 16 + 2 * tig];
                const __half* q1p = &Qs[r1b * LDH + kk * 16 + 2 * tig];
                pb[0] = *(const uint32_t*)q0p;
                pb[1] = *(const uint32_t*)q1p;
                pb[2] = *(const uint32_t*)(q0p + 8);
                pb[3] = *(const uint32_t*)(q1p + 8);
            }
#pragma unroll
            for (int j = 0; j < 8; j++) {
                const __half* vrow = &Vst[(j * 8 + g) * LDH];
                const uint32_t b0 = *(const uint32_t*)&vrow[kk * 16 + 2 * tig];
                const uint32_t b1 = *(const uint32_t*)&vrow[kk * 16 + 2 * tig + 8];
                mma16(o[0][j], pa, b0, b1);
                mma16(o[1][j], pb, b0, b1);
            }
        }
        __syncthreads();
    }

    // ---- normalize + write fp16 g_aoh ----
#pragma unroll
    for (int mf = 0; mf < 2; mf++) {
        const int r0 = rb + mf * 16 + g, r1 = r0 + 8;
        const float inv0 = 1.0f / li[mf][0], inv1 = 1.0f / li[mf][1];
        __half* dst0 = g_aoh + ((size_t)b * SS + (q0 + r0)) * DD + h * HD;
        __half* dst1 = g_aoh + ((size_t)b * SS + (q0 + r1)) * DD + h * HD;
#pragma unroll
        for (int j = 0; j < 8; j++) {
            *(__half2*)&dst0[j * 8 + 2 * tig] =
                __floats2half2_rn(o[mf][j][0] * inv0, o[mf][j][1] * inv0);
            *(__half2*)&dst1[j * 8 + 2 * tig] =
                __floats2half2_rn(o[mf][j][2] * inv1, o[mf][j][3] * inv1);
        }
    }
}

// ---------------------------------------------------------------------------
extern "C" void kernel_launch(void* const* d_in, const int* in_sizes, int n_in,
                              void* d_out, int out_size)
{
    const float* x    = (const float*)d_in[0];
    const int*   mask = (const int*)  d_in[1];
    const float* Wqkv = (const float*)d_in[2];
    const float* bqkv = (const float*)d_in[3];
    const float* Wo   = (const float*)d_in[4];
    const float* bo   = (const float*)d_in[5];
    float* out = (float*)d_out;
    (void)in_sizes; (void)n_in; (void)out_size;

    cudaFuncSetAttribute(attn_k, cudaFuncAttributeMaxDynamicSharedMemorySize,
                         ATTN_SMEM);
    cudaFuncSetAttribute(hgemm_k<0>, cudaFuncAttributeMaxDynamicSharedMemorySize,
                         GSMEM);
    cudaFuncSetAttribute(hgemm_k<1>, cudaFuncAttributeMaxDynamicSharedMemorySize,
                         GSMEM);

    // 0) pre-passes
    prepass_k<<<(PRE_TOT + 255) / 256, 256>>>((const float4*)x, mask);
    tr_h<<<dim3(3 * DD / 32, KK / 32), dim3(32, 8)>>>(Wqkv, 0, 3 * DD);
    tr_h<<<dim3(DD / 32, KK / 32), dim3(32, 8)>>>(Wo, 1, DD);

    // 1) QKV projection (fp16 mma) -> fp16 q/k + transposed v
    {
        dim3 grid(3 * DD / 128, (BB * SS) / 128);
        hgemm_k<0><<<grid, 128, GSMEM>>>(bqkv, nullptr, 3 * DD);
    }

    // 2) Flash attention (fp16 mma) -> g_aoh (fp16)
    attn_k<<<dim3(SS / 128, HH, BB), 128, ATTN_SMEM>>>();

    // 3) Output projection (fp16 mma) -> d_out (fp32)
    {
        dim3 grid(DD / 128, (BB * SS) / 128);
        hgemm_k<1><<<grid, 128, GSMEM>>>(bo, out, DD);
    }
}

// round 14
// speedup vs baseline: 1.7600x; 1.0375x over previous
#include <cuda_runtime.h>
#include <cuda_fp16.h>
#include <mma.h>
#include <cstdint>

#define BB 4
#define SS 1024
#define DD 1024
#define HH 16
#define HD 64
#define KK 1024

// Scratch (__device__ globals — allocation-free rule)
static __device__ __half g_qh[BB * HH * SS * HD];   // fp16 q [bh][S][hd], pre-scaled
static __device__ __half g_kh[BB * HH * SS * HD];   // fp16 k [bh][S][hd]
static __device__ __half g_vth[BB * HH * HD * SS];  // fp16 v TRANSPOSED [bh][hd][S]
static __device__ __half g_xh[BB * SS * DD];        // fp16 x [M][K]
static __device__ __half g_wqkvh[3 * DD * DD];      // fp16 Wqkv^T [N][K]
static __device__ __half g_woh[DD * DD];            // fp16 Wo^T   [N][K]
static __device__ __half g_aoh[BB * SS * DD];       // fp16 attn out [M][K]
static __device__ uint32_t g_mb[BB * SS * (SS / 32)];

__device__ __forceinline__ void cpa16(void* dst, const void* src) {
    unsigned d = (unsigned)__cvta_generic_to_shared(dst);
    asm volatile("cp.async.cg.shared.global [%0], [%1], 16;\n" :: "r"(d), "l"(src));
}
#define CP_COMMIT() asm volatile("cp.async.commit_group;\n" ::)
#define CP_WAIT(N)  asm volatile("cp.async.wait_group %0;\n" :: "n"(N))

// fp16 m16n8k16 mma (A row-major, B col-major), fp32 accum, in place
__device__ __forceinline__ void mma16(float* d, const uint32_t* a,
                                      uint32_t b0, uint32_t b1) {
    asm volatile(
        "mma.sync.aligned.m16n8k16.row.col.f32.f16.f16.f32 "
        "{%0,%1,%2,%3}, {%4,%5,%6,%7}, {%8,%9}, {%0,%1,%2,%3};"
        : "+f"(d[0]), "+f"(d[1]), "+f"(d[2]), "+f"(d[3])
        : "r"(a[0]), "r"(a[1]), "r"(a[2]), "r"(a[3]), "r"(b0), "r"(b1));
}

// ---------------------------------------------------------------------------
// Single fused pre-pass (256 threads/block, one launch):
//   blocks [0, TQ)            : Wqkv 32x32 transpose tiles -> g_wqkvh fp16
//   blocks [TQ, TQ+TO)        : Wo   32x32 transpose tiles -> g_woh fp16
//   blocks [TQ+TO, ...)       : linear work — x->fp16, mask bit-pack
// ---------------------------------------------------------------------------
#define N4_X  (BB * SS * DD / 4)
#define N_MW  (BB * SS * (SS / 32))
#define TQ_TILES ((3 * DD / 32) * (KK / 32))   // 3072
#define TO_TILES ((DD / 32) * (KK / 32))       // 1024
#define LIN_BLOCKS ((N4_X + N_MW + 255) / 256)
#define PRE_BLOCKS (TQ_TILES + TO_TILES + LIN_BLOCKS)

__global__ void __launch_bounds__(256) prepass_k(
    const float4* __restrict__ x4, const float* __restrict__ Wqkv,
    const float* __restrict__ Wo, const int* __restrict__ mask)
{
    __shared__ float tbuf[32][33];
    const int bid = blockIdx.x;
    const int tid = threadIdx.x;

    if (bid < TQ_TILES + TO_TILES) {
        const bool isQ = bid < TQ_TILES;
        const int t = isQ ? bid : bid - TQ_TILES;
        const int C = isQ ? 3 * DD : DD;
        const float* src = isQ ? Wqkv : Wo;
        __half* dst = isQ ? g_wqkvh : g_woh;
        const int bx = (t % (C / 32)) * 32;   // col (N dim)
        const int by = (t / (C / 32)) * 32;   // row (K dim)
        const int tx = tid & 31, ty = tid >> 5;
#pragma unroll
        for (int i = 0; i < 4; i++)
            tbuf[ty + i * 8][tx] =
                src[(size_t)(by + ty + i * 8) * C + bx + tx];
        __syncthreads();
#pragma unroll
        for (int i = 0; i < 4; i++)
            dst[(size_t)(bx + ty + i * 8) * KK + by + tx] =
                __float2half_rn(tbuf[tx][ty + i * 8]);
    } else {
        const int i = (bid - TQ_TILES - TO_TILES) * 256 + tid;
        if (i < N4_X) {
            float4 v = x4[i];
            __half2* dst = (__half2*)g_xh + i * 2;
            dst[0] = __floats2half2_rn(v.x, v.y);
            dst[1] = __floats2half2_rn(v.z, v.w);
        } else if (i < N4_X + N_MW) {
            int m = i - N4_X;
            const int4* src = (const int4*)(mask + (size_t)m * 32);
            uint32_t w = 0;
#pragma unroll
            for (int k = 0; k < 8; k++) {
                int4 v = src[k];
                w |= (v.x != 0 ? 1u : 0u) << (k * 4 + 0);
                w |= (v.y != 0 ? 1u : 0u) << (k * 4 + 1);
                w |= (v.z != 0 ? 1u : 0u) << (k * 4 + 2);
                w |= (v.w != 0 ? 1u : 0u) << (k * 4 + 3);
            }
            g_mb[m] = w;
        }
    }
}

// ---------------------------------------------------------------------------
// fp16 mma.sync GEMM. CTA 128x128, BK=64 halfs (4 k16 steps), 128 thr,
// warp tile 64x64, 3-stage cp.async ring, 1 barrier per 64-deep slab.
// Stage: A[128][72] + B[128][72] halfs = 36864 B (144B row stride, frag
// banks 4g+tig conflict-free). A = [M][K] fp16, B = [N][K] fp16.
// MODE 0: A=g_xh,  B=g_wqkvh -> fp16 q(*0.125)/k + TRANSPOSED v
// MODE 1: A=g_aoh, B=g_woh   -> C = acc + bias (fp32 final out)
// ---------------------------------------------------------------------------
#define HSTG 18432                 // halfs per stage
#define GSMEM (3 * HSTG * 2)       // 110592 bytes

template <int MODE>
__global__ void __launch_bounds__(128, 2) hgemm_k(
    const float* __restrict__ bias, float* __restrict__ C, int N)
{
    extern __shared__ __half hsm[];

    const int tid = threadIdx.x, lane = tid & 31, warp = tid >> 5;
    const int g = lane >> 2, tig = lane & 3;
    const int wm = (warp >> 1) * 64, wn = (warp & 1) * 64;
    const int m0 = blockIdx.y * 128, n0 = blockIdx.x * 128;

    const __half* Ap = (MODE == 0) ? (const __half*)g_xh : (const __half*)g_aoh;
    const __half* Bp = (MODE == 0) ? (const __half*)g_wqkvh : (const __half*)g_woh;

    auto issue = [&](int st, int k0) {
        __half* As = hsm + st * HSTG;
        __half* Bs = As + 9216;
#pragma unroll
        for (int v = 0; v < 8; v++) {
            int id = tid + v * 128;           // 0..1023
            int row = id >> 3, c = id & 7;    // row 0..127, 16B chunk
            cpa16(&As[row * 72 + c * 8],
                  Ap + (size_t)(m0 + row) * KK + k0 + c * 8);
            cpa16(&Bs[row * 72 + c * 8],
                  Bp + (size_t)(n0 + row) * KK + k0 + c * 8);
        }
    };

    float d[4][8][4];
#pragma unroll
    for (int mf = 0; mf < 4; mf++)
#pragma unroll
        for (int nf = 0; nf < 8; nf++)
#pragma unroll
            for (int c = 0; c < 4; c++) d[mf][nf][c] = 0.0f;

    issue(0, 0);  CP_COMMIT();
    issue(1, 64); CP_COMMIT();

    const int NI = KK / 64;
    for (int i = 0; i < NI; i++) {
        const int st = i % 3;
        CP_WAIT(1);
        __syncthreads();
        if (i + 2 < NI) issue((i + 2) % 3, (i + 2) * 64);
        CP_COMMIT();

        const __half* As = hsm + st * HSTG;
        const __half* Bs = As + 9216;

        uint32_t af[2][4][4], bf[2][8][2];
        auto ldA = [&](int buf, int kk) {
#pragma unroll
            for (int mf = 0; mf < 4; mf++) {
                const __half* p0 = &As[(wm + mf * 16 + g) * 72 + kk * 16 + 2 * tig];
                const __half* p1 = p0 + 8 * 72;
                af[buf][mf][0] = *(const uint32_t*)p0;
                af[buf][mf][1] = *(const uint32_t*)p1;
                af[buf][mf][2] = *(const uint32_t*)(p0 + 8);
                af[buf][mf][3] = *(const uint32_t*)(p1 + 8);
            }
        };
        auto ldB = [&](int buf, int kk) {
#pragma unroll
            for (int nf = 0; nf < 8; nf++) {
                const __half* p = &Bs[(wn + nf * 8 + g) * 72 + kk * 16 + 2 * tig];
                bf[buf][nf][0] = *(const uint32_t*)p;
                bf[buf][nf][1] = *(const uint32_t*)(p + 8);
            }
        };
        ldA(0, 0); ldB(0, 0);
#pragma unroll
        for (int kk = 0; kk < 4; kk++) {
            const int cur = kk & 1;
            if (kk < 3) { ldA(cur ^ 1, kk + 1); ldB(cur ^ 1, kk + 1); }
#pragma unroll
            for (int mf = 0; mf < 4; mf++)
#pragma unroll
                for (int nf = 0; nf < 8; nf++)
                    mma16(d[mf][nf], af[cur][mf], bf[cur][nf][0], bf[cur][nf][1]);
        }
    }

    // ---- epilogue ----
#pragma unroll
    for (int mf = 0; mf < 4; mf++) {
        const int m = m0 + wm + mf * 16 + g;
        const int bb = m >> 10, srow = m & 1023;
#pragma unroll
        for (int nf = 0; nf < 8; nf++) {
            const int col0 = n0 + wn + nf * 8 + 2 * tig;
            const float b0 = bias[col0], b1 = bias[col0 + 1];
            float v0 = d[mf][nf][0] + b0, v1 = d[mf][nf][1] + b1;
            float v2 = d[mf][nf][2] + b0, v3 = d[mf][nf][3] + b1;

            if (MODE == 0) {
                const int h = col0 / 192;
                const int rr = col0 - h * 192;
                const int seg = rr >> 6;
                const int db = rr & 63;
                const size_t bhb = (size_t)(bb * HH + h);
                if (seg == 2) {
                    __half* vd = g_vth + (bhb * HD + db) * SS;
                    vd[srow]          = __float2half_rn(v0);
                    vd[SS + srow]     = __float2half_rn(v1);
                    vd[srow + 8]      = __float2half_rn(v2);
                    vd[SS + srow + 8] = __float2half_rn(v3);
                } else {
                    __half* dst = (seg == 0) ? g_qh : g_kh;
                    const float sc = (seg == 0) ? 0.125f : 1.0f;
                    const size_t idx = (bhb * SS + srow) * HD + db;
                    *(__half2*)&dst[idx] =
                        __floats2half2_rn(v0 * sc, v1 * sc);
                    *(__half2*)&dst[idx + 8 * HD] =
                        __floats2half2_rn(v2 * sc, v3 * sc);
                }
            } else {
                float* dst = C + (size_t)m * N + col0;
                *(float2*)dst           = make_float2(v0, v1);
                *(float2*)(dst + 8 * N) = make_float2(v2, v3);
            }
        }
    }
}

// ---------------------------------------------------------------------------
// Flash attention FA2, full fp16 mma (m16n8k16) — unchanged from round 13.
// smem halves: Qs[128][72] | Ks[2][64][72] | Vt[2][64][72]. Total 55296 B.
// ---------------------------------------------------------------------------
#define LDH 72
#define NT (SS / 64)
#define ATTN_SMEM (27648 * 2)

__global__ void __launch_bounds__(128, 2) attn_k(void)
{
    extern __shared__ __half hsm[];
    __half* Qs = hsm;            // q staging, then P buffer
    __half* Ks = hsm + 9216;     // stage stride 4608 halves
    __half* Vs = hsm + 18432;    // transposed V tiles

    const int tid = threadIdx.x, lane = tid & 31, warp = tid >> 5;
    const int g = lane >> 2, tig = lane & 3;
    const int q0 = blockIdx.x * 128;
    const int h = blockIdx.y, b = blockIdx.z;
    const size_t bh = (size_t)(b * HH + h);
    const __half* qb  = g_qh  + bh * SS * HD;
    const __half* kb  = g_kh  + bh * SS * HD;
    const __half* vtb = g_vth + bh * HD * SS;

#pragma unroll
    for (int j = 0; j < 8; j++) {
        int idx = tid + j * 128;
        int r = idx >> 3, c = idx & 7;
        cpa16(&Qs[r * LDH + c * 8], qb + (size_t)(q0 + r) * HD + c * 8);
    }
#pragma unroll
    for (int j = 0; j < 4; j++) {
        int idx = tid + j * 128;
        int r = idx >> 3, c = idx & 7;
        cpa16(&Ks[r * LDH + c * 8], kb + (size_t)r * HD + c * 8);
        cpa16(&Vs[r * LDH + c * 8], vtb + (size_t)r * SS + c * 8);
    }
    CP_COMMIT();
    CP_WAIT(0);
    __syncthreads();

    const int rb = 32 * warp;
    const int r0a = rb + g,      r1a = rb + g + 8;
    const int r0b = rb + 16 + g, r1b = rb + 16 + g + 8;

    uint32_t qf[2][4][4];
#pragma unroll
    for (int mf = 0; mf < 2; mf++) {
        const int r0 = rb + mf * 16 + g, r1 = r0 + 8;
#pragma unroll
        for (int kk = 0; kk < 4; kk++) {
            const __half* p0 = &Qs[r0 * LDH + kk * 16 + 2 * tig];
            const __half* p1 = &Qs[r1 * LDH + kk * 16 + 2 * tig];
            qf[mf][kk][0] = *(const uint32_t*)p0;
            qf[mf][kk][1] = *(const uint32_t*)p1;
            qf[mf][kk][2] = *(const uint32_t*)(p0 + 8);
            qf[mf][kk][3] = *(const uint32_t*)(p1 + 8);
        }
    }
    __syncthreads();   // Qs is now the P buffer

    float o[2][8][4];
#pragma unroll
    for (int mf = 0; mf < 2; mf++)
#pragma unroll
        for (int j = 0; j < 8; j++)
#pragma unroll
            for (int c = 0; c < 4; c++) o[mf][j][c] = 0.0f;
    float mi[2][2], li[2][2];
#pragma unroll
    for (int mf = 0; mf < 2; mf++) {
        mi[mf][0] = mi[mf][1] = -1e30f;
        li[mf][0] = li[mf][1] = 0.0f;
    }

    const uint32_t* mb0 = g_mb + ((size_t)b * SS + (q0 + r0a)) * 32;
    const uint32_t* mb1 = g_mb + ((size_t)b * SS + (q0 + r1a)) * 32;
    const uint32_t* mb2 = g_mb + ((size_t)b * SS + (q0 + r0b)) * 32;
    const uint32_t* mb3 = g_mb + ((size_t)b * SS + (q0 + r1b)) * 32;

    for (int t = 0; t < NT; t++) {
        const int st = t & 1;
        if (t + 1 < NT) {
            const __half* kb2  = kb  + (size_t)(t + 1) * 64 * HD;
            const __half* vtb2 = vtb + (size_t)(t + 1) * 64;
            __half* Kd = Ks + (st ^ 1) * 4608;
            __half* Vd = Vs + (st ^ 1) * 4608;
#pragma unroll
            for (int j = 0; j < 4; j++) {
                int idx = tid + j * 128;
                int r = idx >> 3, c = idx & 7;
                cpa16(&Kd[r * LDH + c * 8], kb2 + (size_t)r * HD + c * 8);
                cpa16(&Vd[r * LDH + c * 8], vtb2 + (size_t)r * SS + c * 8);
            }
        }
        CP_COMMIT();

        uint2 mw[4];
        mw[0] = *(const uint2*)(mb0 + t * 2);
        mw[1] = *(const uint2*)(mb1 + t * 2);
        mw[2] = *(const uint2*)(mb2 + t * 2);
        mw[3] = *(const uint2*)(mb3 + t * 2);

        CP_WAIT(1);
        __syncthreads();

        const __half* Kst = Ks + st * 4608;
        const __half* Vst = Vs + st * 4608;

        float s[2][8][4];
#pragma unroll
        for (int j = 0; j < 8; j++) {
            s[0][j][0] = s[0][j][1] = s[0][j][2] = s[0][j][3] = 0.0f;
            s[1][j][0] = s[1][j][1] = s[1][j][2] = s[1][j][3] = 0.0f;
            const __half* krow = &Kst[(j * 8 + g) * LDH];
#pragma unroll
            for (int kk = 0; kk < 4; kk++) {
                const uint32_t b0 = *(const uint32_t*)&krow[kk * 16 + 2 * tig];
                const uint32_t b1 = *(const uint32_t*)&krow[kk * 16 + 2 * tig + 8];
                mma16(s[0][j], qf[0][kk], b0, b1);
                mma16(s[1][j], qf[1][kk], b0, b1);
            }
        }

#pragma unroll
        for (int mf = 0; mf < 2; mf++) {
#pragma unroll
            for (int j = 0; j < 8; j++) {
                const int bit = (j * 8 + 2 * tig) & 31;
                const uint32_t wa = (j < 4) ? mw[mf * 2].x     : mw[mf * 2].y;
                const uint32_t wb = (j < 4) ? mw[mf * 2 + 1].x : mw[mf * 2 + 1].y;
                if (!((wa >> bit) & 1))       s[mf][j][0] = -1e20f;
                if (!((wa >> (bit + 1)) & 1)) s[mf][j][1] = -1e20f;
                if (!((wb >> bit) & 1))       s[mf][j][2] = -1e20f;
                if (!((wb >> (bit + 1)) & 1)) s[mf][j][3] = -1e20f;
            }
        }

#pragma unroll
        for (int mf = 0; mf < 2; mf++) {
            float mx0 = s[mf][0][0], mx1 = s[mf][0][2];
#pragma unroll
            for (int j = 0; j < 8; j++) {
                mx0 = fmaxf(mx0, fmaxf(s[mf][j][0], s[mf][j][1]));
                mx1 = fmaxf(mx1, fmaxf(s[mf][j][2], s[mf][j][3]));
            }
            mx0 = fmaxf(mx0, __shfl_xor_sync(0xffffffffu, mx0, 1));
            mx0 = fmaxf(mx0, __shfl_xor_sync(0xffffffffu, mx0, 2));
            mx1 = fmaxf(mx1, __shfl_xor_sync(0xffffffffu, mx1, 1));
            mx1 = fmaxf(mx1, __shfl_xor_sync(0xffffffffu, mx1, 2));
            const float mn0 = fmaxf(mi[mf][0], mx0);
            const float mn1 = fmaxf(mi[mf][1], mx1);
            const float a0 = __expf(mi[mf][0] - mn0);
            const float a1 = __expf(mi[mf][1] - mn1);
            float rs0 = 0.0f, rs1 = 0.0f;
            const int rr0 = rb + mf * 16 + g, rr1 = rr0 + 8;
#pragma unroll
            for (int j = 0; j < 8; j++) {
                s[mf][j][0] = __expf(s[mf][j][0] - mn0);
                s[mf][j][1] = __expf(s[mf][j][1] - mn0);
                s[mf][j][2] = __expf(s[mf][j][2] - mn1);
                s[mf][j][3] = __expf(s[mf][j][3] - mn1);
                rs0 += s[mf][j][0] + s[mf][j][1];
                rs1 += s[mf][j][2] + s[mf][j][3];
                *(__half2*)&Qs[rr0 * LDH + j * 8 + 2 * tig] =
                    __floats2half2_rn(s[mf][j][0], s[mf][j][1]);
                *(__half2*)&Qs[rr1 * LDH + j * 8 + 2 * tig] =
                    __floats2half2_rn(s[mf][j][2], s[mf][j][3]);
            }
            rs0 += __shfl_xor_sync(0xffffffffu, rs0, 1);
            rs0 += __shfl_xor_sync(0xffffffffu, rs0, 2);
            rs1 += __shfl_xor_sync(0xffffffffu, rs1, 1);
            rs1 += __shfl_xor_sync(0xffffffffu, rs1, 2);
            li[mf][0] = li[mf][0] * a0 + rs0;
            li[mf][1] = li[mf][1] * a1 + rs1;
            mi[mf][0] = mn0; mi[mf][1] = mn1;
#pragma unroll
            for (int j = 0; j < 8; j++) {
                o[mf][j][0] *= a0; o[mf][j][1] *= a0;
                o[mf][j][2] *= a1; o[mf][j][3] *= a1;
            }
        }
        __syncwarp();

#pragma unroll
        for (int kk = 0; kk < 4; kk++) {
            uint32_t pa[4], pb[4];
            {
                const __half* p0 = &Qs[r0a * LDH + kk * 16 + 2 * tig];
                const __half* p1 = &Qs[r1a * LDH + kk * 16 + 2 * tig];
                pa[0] = *(const uint32_t*)p0;
                pa[1] = *(const uint32_t*)p1;
                pa[2] = *(const uint32_t*)(p0 + 8);
                pa[3] = *(const uint32_t*)(p1 + 8);
                const __half* q0p = &Qs[r0b * LDH + kk * 16 + 2 * tig];
                const __half* q1p = &Qs[r1b * LDH + kk * 16 + 2 * tig];
                pb[0] = *(const uint32_t*)q0p;
                pb[1] = *(const uint32_t*)q1p;
                pb[2] = *(const uint32_t*)(q0p + 8);
                pb[3] = *(const uint32_t*)(q1p + 8);
            }
#pragma unroll
            for (int j = 0; j < 8; j++) {
                const __half* vrow = &Vst[(j * 8 + g) * LDH];
                const uint32_t b0 = *(const uint32_t*)&vrow[kk * 16 + 2 * tig];
                const uint32_t b1 = *(const uint32_t*)&vrow[kk * 16 + 2 * tig + 8];
                mma16(o[0][j], pa, b0, b1);
                mma16(o[1][j], pb, b0, b1);
            }
        }
        __syncthreads();
    }

#pragma unroll
    for (int mf = 0; mf < 2; mf++) {
        const int r0 = rb + mf * 16 + g, r1 = r0 + 8;
        const float inv0 = 1.0f / li[mf][0], inv1 = 1.0f / li[mf][1];
        __half* dst0 = g_aoh + ((size_t)b * SS + (q0 + r0)) * DD + h * HD;
        __half* dst1 = g_aoh + ((size_t)b * SS + (q0 + r1)) * DD + h * HD;
#pragma unroll
        for (int j = 0; j < 8; j++) {
            *(__half2*)&dst0[j * 8 + 2 * tig] =
                __floats2half2_rn(o[mf][j][0] * inv0, o[mf][j][1] * inv0);
            *(__half2*)&dst1[j * 8 + 2 * tig] =
                __floats2half2_rn(o[mf][j][2] * inv1, o[mf][j][3] * inv1);
        }
    }
}

// ---------------------------------------------------------------------------
extern "C" void kernel_launch(void* const* d_in, const int* in_sizes, int n_in,
                              void* d_out, int out_size)
{
    const float* x    = (const float*)d_in[0];
    const int*   mask = (const int*)  d_in[1];
    const float* Wqkv = (const float*)d_in[2];
    const float* bqkv = (const float*)d_in[3];
    const float* Wo   = (const float*)d_in[4];
    const float* bo   = (const float*)d_in[5];
    float* out = (float*)d_out;
    (void)in_sizes; (void)n_in; (void)out_size;

    cudaFuncSetAttribute(attn_k, cudaFuncAttributeMaxDynamicSharedMemorySize,
                         ATTN_SMEM);
    cudaFuncSetAttribute(hgemm_k<0>, cudaFuncAttributeMaxDynamicSharedMemorySize,
                         GSMEM);
    cudaFuncSetAttribute(hgemm_k<1>, cudaFuncAttributeMaxDynamicSharedMemorySize,
                         GSMEM);

    // 0) single fused pre-pass
    prepass_k<<<PRE_BLOCKS, 256>>>((const float4*)x, Wqkv, Wo, mask);

    // 1) QKV projection (fp16 mma, BK=64) -> fp16 q/k + transposed v
    {
        dim3 grid(3 * DD / 128, (BB * SS) / 128);
        hgemm_k<0><<<grid, 128, GSMEM>>>(bqkv, nullptr, 3 * DD);
    }

    // 2) Flash attention (fp16 mma) -> g_aoh (fp16)
    attn_k<<<dim3(SS / 128, HH, BB), 128, ATTN_SMEM>>>();

    // 3) Output projection (fp16 mma, BK=64) -> d_out (fp32)
    {
        dim3 grid(DD / 128, (BB * SS) / 128);
        hgemm_k<1><<<grid, 128, GSMEM>>>(bo, out, DD);
    }
}

// round 15
// speedup vs baseline: 1.8030x; 1.0244x over previous
#include <cuda_runtime.h>
#include <cuda_fp16.h>
#include <mma.h>
#include <cstdint>

#define BB 4
#define SS 1024
#define DD 1024
#define HH 16
#define HD 64
#define KK 1024

// Scratch (__device__ globals — allocation-free rule)
static __device__ __half g_qh[BB * HH * SS * HD];   // fp16 q, pre-scaled
static __device__ __half g_kh[BB * HH * SS * HD];   // fp16 k
static __device__ __half g_vth[BB * HH * HD * SS];  // fp16 v TRANSPOSED [bh][hd][S]
static __device__ __half g_xh[BB * SS * DD];        // fp16 x [M][K]
static __device__ __half g_wqkvh[3 * DD * DD];      // fp16 Wqkv^T [N][K]
static __device__ __half g_woh[DD * DD];            // fp16 Wo^T   [N][K]
static __device__ __half g_aoh[BB * SS * DD];       // fp16 attn out [M][K]
static __device__ uint32_t g_mb[BB * SS * (SS / 32)];

__device__ __forceinline__ void cpa16(void* dst, const void* src) {
    unsigned d = (unsigned)__cvta_generic_to_shared(dst);
    asm volatile("cp.async.cg.shared.global [%0], [%1], 16;\n" :: "r"(d), "l"(src));
}
#define CP_COMMIT() asm volatile("cp.async.commit_group;\n" ::)
#define CP_WAIT(N)  asm volatile("cp.async.wait_group %0;\n" :: "n"(N))

// fp16 m16n8k16 mma (A row-major, B col-major), fp32 accum, in place
__device__ __forceinline__ void mma16(float* d, const uint32_t* a,
                                      uint32_t b0, uint32_t b1) {
    asm volatile(
        "mma.sync.aligned.m16n8k16.row.col.f32.f16.f16.f32 "
        "{%0,%1,%2,%3}, {%4,%5,%6,%7}, {%8,%9}, {%0,%1,%2,%3};"
        : "+f"(d[0]), "+f"(d[1]), "+f"(d[2]), "+f"(d[3])
        : "r"(a[0]), "r"(a[1]), "r"(a[2]), "r"(a[3]), "r"(b0), "r"(b1));
}

// ldmatrix x4 (non-transposed)
__device__ __forceinline__ void ldsm4(uint32_t* r, uint32_t addr) {
    asm volatile(
        "ldmatrix.sync.aligned.m8n8.x4.shared.b16 {%0,%1,%2,%3}, [%4];"
        : "=r"(r[0]), "=r"(r[1]), "=r"(r[2]), "=r"(r[3]) : "r"(addr));
}

// ---------------------------------------------------------------------------
// Single fused pre-pass (one launch): weight transposes + x->fp16 + mask pack
// ---------------------------------------------------------------------------
#define N4_X  (BB * SS * DD / 4)
#define N_MW  (BB * SS * (SS / 32))
#define TQ_TILES ((3 * DD / 32) * (KK / 32))
#define TO_TILES ((DD / 32) * (KK / 32))
#define LIN_BLOCKS ((N4_X + N_MW + 255) / 256)
#define PRE_BLOCKS (TQ_TILES + TO_TILES + LIN_BLOCKS)

__global__ void __launch_bounds__(256) prepass_k(
    const float4* __restrict__ x4, const float* __restrict__ Wqkv,
    const float* __restrict__ Wo, const int* __restrict__ mask)
{
    __shared__ float tbuf[32][33];
    const int bid = blockIdx.x;
    const int tid = threadIdx.x;

    if (bid < TQ_TILES + TO_TILES) {
        const bool isQ = bid < TQ_TILES;
        const int t = isQ ? bid : bid - TQ_TILES;
        const int C = isQ ? 3 * DD : DD;
        const float* src = isQ ? Wqkv : Wo;
        __half* dst = isQ ? g_wqkvh : g_woh;
        const int bx = (t % (C / 32)) * 32;
        const int by = (t / (C / 32)) * 32;
        const int tx = tid & 31, ty = tid >> 5;
#pragma unroll
        for (int i = 0; i < 4; i++)
            tbuf[ty + i * 8][tx] =
                src[(size_t)(by + ty + i * 8) * C + bx + tx];
        __syncthreads();
#pragma unroll
        for (int i = 0; i < 4; i++)
            dst[(size_t)(bx + ty + i * 8) * KK + by + tx] =
                __float2half_rn(tbuf[tx][ty + i * 8]);
    } else {
        const int i = (bid - TQ_TILES - TO_TILES) * 256 + tid;
        if (i < N4_X) {
            float4 v = x4[i];
            __half2* dst = (__half2*)g_xh + i * 2;
            dst[0] = __floats2half2_rn(v.x, v.y);
            dst[1] = __floats2half2_rn(v.z, v.w);
        } else if (i < N4_X + N_MW) {
            int m = i - N4_X;
            const int4* src = (const int4*)(mask + (size_t)m * 32);
            uint32_t w = 0;
#pragma unroll
            for (int k = 0; k < 8; k++) {
                int4 v = src[k];
                w |= (v.x != 0 ? 1u : 0u) << (k * 4 + 0);
                w |= (v.y != 0 ? 1u : 0u) << (k * 4 + 1);
                w |= (v.z != 0 ? 1u : 0u) << (k * 4 + 2);
                w |= (v.w != 0 ? 1u : 0u) << (k * 4 + 3);
            }
            g_mb[m] = w;
        }
    }
}

// ---------------------------------------------------------------------------
// fp16 mma.sync GEMM with ldmatrix fragment loads. CTA 128x128, BK=64,
// 128 thr, warp tile 64x64, 3-stage cp.async ring, 1 barrier/slab.
// Stage: A[128][72] + B[128][72] halfs. Rows 144B-strided; ldmatrix phase
// banks 4r mod 32 — conflict-free.
// ---------------------------------------------------------------------------
#define HSTG 18432
#define GSMEM (3 * HSTG * 2)

template <int MODE>
__global__ void __launch_bounds__(128, 2) hgemm_k(
    const float* __restrict__ bias, float* __restrict__ C, int N)
{
    extern __shared__ __half hsm[];

    const int tid = threadIdx.x, lane = tid & 31, warp = tid >> 5;
    const int g = lane >> 2, tig = lane & 3;
    const int wm = (warp >> 1) * 64, wn = (warp & 1) * 64;
    const int m0 = blockIdx.y * 128, n0 = blockIdx.x * 128;

    const __half* Ap = (MODE == 0) ? (const __half*)g_xh : (const __half*)g_aoh;
    const __half* Bp = (MODE == 0) ? (const __half*)g_wqkvh : (const __half*)g_woh;

    const uint32_t smem0 = (uint32_t)__cvta_generic_to_shared(hsm);
    // ldmatrix per-lane offsets (in halves, converted to bytes at use)
    const int aoff = (wm + (lane & 15)) * 72 + (lane >> 4) * 8;
    const int boff = (wn + ((lane >> 4) & 1) * 8 + (lane & 7)) * 72 +
                     ((lane >> 3) & 1) * 8;

    auto issue = [&](int st, int k0) {
        __half* As = hsm + st * HSTG;
        __half* Bs = As + 9216;
#pragma unroll
        for (int v = 0; v < 8; v++) {
            int id = tid + v * 128;
            int row = id >> 3, c = id & 7;
            cpa16(&As[row * 72 + c * 8],
                  Ap + (size_t)(m0 + row) * KK + k0 + c * 8);
            cpa16(&Bs[row * 72 + c * 8],
                  Bp + (size_t)(n0 + row) * KK + k0 + c * 8);
        }
    };

    float d[4][8][4];
#pragma unroll
    for (int mf = 0; mf < 4; mf++)
#pragma unroll
        for (int nf = 0; nf < 8; nf++)
#pragma unroll
            for (int c = 0; c < 4; c++) d[mf][nf][c] = 0.0f;

    issue(0, 0);  CP_COMMIT();
    issue(1, 64); CP_COMMIT();

    const int NI = KK / 64;
    for (int i = 0; i < NI; i++) {
        const int st = i % 3;
        CP_WAIT(1);
        __syncthreads();
        if (i + 2 < NI) issue((i + 2) % 3, (i + 2) * 64);
        CP_COMMIT();

        const uint32_t Ab = smem0 + (st * HSTG) * 2;
        const uint32_t Bb = Ab + 9216 * 2;
        const uint32_t Aaddr = Ab + aoff * 2;
        const uint32_t Baddr = Bb + boff * 2;

        uint32_t af[2][4][4], bf[2][4][4];   // bf[..][nfp][4] = b0,b1 of 2 nf
        auto ldFrags = [&](int buf, int kk) {
#pragma unroll
            for (int mf = 0; mf < 4; mf++)
                ldsm4(af[buf][mf], Aaddr + (mf * 16 * 72 + kk * 16) * 2);
#pragma unroll
            for (int nfp = 0; nfp < 4; nfp++)
                ldsm4(bf[buf][nfp], Baddr + (nfp * 16 * 72 + kk * 16) * 2);
        };
        ldFrags(0, 0);
#pragma unroll
        for (int kk = 0; kk < 4; kk++) {
            const int cur = kk & 1;
            if (kk < 3) ldFrags(cur ^ 1, kk + 1);
#pragma unroll
            for (int mf = 0; mf < 4; mf++)
#pragma unroll
                for (int nfp = 0; nfp < 4; nfp++) {
                    mma16(d[mf][nfp * 2],     af[cur][mf],
                          bf[cur][nfp][0], bf[cur][nfp][1]);
                    mma16(d[mf][nfp * 2 + 1], af[cur][mf],
                          bf[cur][nfp][2], bf[cur][nfp][3]);
                }
        }
    }

    // ---- epilogue ----
#pragma unroll
    for (int mf = 0; mf < 4; mf++) {
        const int m = m0 + wm + mf * 16 + g;
        const int bb = m >> 10, srow = m & 1023;
#pragma unroll
        for (int nf = 0; nf < 8; nf++) {
            const int col0 = n0 + wn + nf * 8 + 2 * tig;
            const float b0 = bias[col0], b1 = bias[col0 + 1];
            float v0 = d[mf][nf][0] + b0, v1 = d[mf][nf][1] + b1;
            float v2 = d[mf][nf][2] + b0, v3 = d[mf][nf][3] + b1;

            if (MODE == 0) {
                const int h = col0 / 192;
                const int rr = col0 - h * 192;
                const int seg = rr >> 6;
                const int db = rr & 63;
                const size_t bhb = (size_t)(bb * HH + h);
                if (seg == 2) {
                    __half* vd = g_vth + (bhb * HD + db) * SS;
                    vd[srow]          = __float2half_rn(v0);
                    vd[SS + srow]     = __float2half_rn(v1);
                    vd[srow + 8]      = __float2half_rn(v2);
                    vd[SS + srow + 8] = __float2half_rn(v3);
                } else {
                    __half* dst = (seg == 0) ? g_qh : g_kh;
                    const float sc = (seg == 0) ? 0.125f : 1.0f;
                    const size_t idx = (bhb * SS + srow) * HD + db;
                    *(__half2*)&dst[idx] =
                        __floats2half2_rn(v0 * sc, v1 * sc);
                    *(__half2*)&dst[idx + 8 * HD] =
                        __floats2half2_rn(v2 * sc, v3 * sc);
                }
            } else {
                float* dst = C + (size_t)m * N + col0;
                *(float2*)dst           = make_float2(v0, v1);
                *(float2*)(dst + 8 * N) = make_float2(v2, v3);
            }
        }
    }
}

// ---------------------------------------------------------------------------
// Flash attention FA2, fp16 mma + ldmatrix fragment loads.
// smem halves: Qs[128][72] | Ks[2][64][72] | Vt[2][64][72]. 55296 B.
// ---------------------------------------------------------------------------
#define LDH 72
#define NT (SS / 64)
#define ATTN_SMEM (27648 * 2)

__global__ void __launch_bounds__(128, 2) attn_k(void)
{
    extern __shared__ __half hsm[];
    __half* Qs = hsm;            // q staging, then P buffer
    __half* Ks = hsm + 9216;
    __half* Vs = hsm + 18432;

    const int tid = threadIdx.x, lane = tid & 31, warp = tid >> 5;
    const int g = lane >> 2, tig = lane & 3;
    const int q0 = blockIdx.x * 128;
    const int h = blockIdx.y, b = blockIdx.z;
    const size_t bh = (size_t)(b * HH + h);
    const __half* qb  = g_qh  + bh * SS * HD;
    const __half* kb  = g_kh  + bh * SS * HD;
    const __half* vtb = g_vth + bh * HD * SS;

    const uint32_t smem0 = (uint32_t)__cvta_generic_to_shared(hsm);
    const uint32_t Qb = smem0;
    // A-pattern lane offset (Q frags / P frags): rows rb + lane&15
    const int rb = 32 * warp;
    const int aoff = (rb + (lane & 15)) * LDH + (lane >> 4) * 8;
    // B-pattern lane offset (K / V frags)
    const int boff = (((lane >> 4) & 1) * 8 + (lane & 7)) * LDH +
                     ((lane >> 3) & 1) * 8;

#pragma unroll
    for (int j = 0; j < 8; j++) {
        int idx = tid + j * 128;
        int r = idx >> 3, c = idx & 7;
        cpa16(&Qs[r * LDH + c * 8], qb + (size_t)(q0 + r) * HD + c * 8);
    }
#pragma unroll
    for (int j = 0; j < 4; j++) {
        int idx = tid + j * 128;
        int r = idx >> 3, c = idx & 7;
        cpa16(&Ks[r * LDH + c * 8], kb + (size_t)r * HD + c * 8);
        cpa16(&Vs[r * LDH + c * 8], vtb + (size_t)r * SS + c * 8);
    }
    CP_COMMIT();
    CP_WAIT(0);
    __syncthreads();

    // Q A-frags via ldmatrix
    uint32_t qf[2][4][4];
#pragma unroll
    for (int mf = 0; mf < 2; mf++)
#pragma unroll
        for (int kk = 0; kk < 4; kk++)
            ldsm4(qf[mf][kk], Qb + (aoff + mf * 16 * LDH + kk * 16) * 2);
    __syncthreads();   // Qs is now the P buffer

    float o[2][8][4];
#pragma unroll
    for (int mf = 0; mf < 2; mf++)
#pragma unroll
        for (int j = 0; j < 8; j++)
#pragma unroll
            for (int c = 0; c < 4; c++) o[mf][j][c] = 0.0f;
    float mi[2][2], li[2][2];
#pragma unroll
    for (int mf = 0; mf < 2; mf++) {
        mi[mf][0] = mi[mf][1] = -1e30f;
        li[mf][0] = li[mf][1] = 0.0f;
    }

    const int r0a = rb + g,      r1a = rb + g + 8;
    const int r0b = rb + 16 + g, r1b = rb + 16 + g + 8;
    const uint32_t* mb0 = g_mb + ((size_t)b * SS + (q0 + r0a)) * 32;
    const uint32_t* mb1 = g_mb + ((size_t)b * SS + (q0 + r1a)) * 32;
    const uint32_t* mb2 = g_mb + ((size_t)b * SS + (q0 + r0b)) * 32;
    const uint32_t* mb3 = g_mb + ((size_t)b * SS + (q0 + r1b)) * 32;

    for (int t = 0; t < NT; t++) {
        const int st = t & 1;
        if (t + 1 < NT) {
            const __half* kb2  = kb  + (size_t)(t + 1) * 64 * HD;
            const __half* vtb2 = vtb + (size_t)(t + 1) * 64;
            __half* Kd = Ks + (st ^ 1) * 4608;
            __half* Vd = Vs + (st ^ 1) * 4608;
#pragma unroll
            for (int j = 0; j < 4; j++) {
                int idx = tid + j * 128;
                int r = idx >> 3, c = idx & 7;
                cpa16(&Kd[r * LDH + c * 8], kb2 + (size_t)r * HD + c * 8);
                cpa16(&Vd[r * LDH + c * 8], vtb2 + (size_t)r * SS + c * 8);
            }
        }
        CP_COMMIT();

        uint2 mw[4];
        mw[0] = *(const uint2*)(mb0 + t * 2);
        mw[1] = *(const uint2*)(mb1 + t * 2);
        mw[2] = *(const uint2*)(mb2 + t * 2);
        mw[3] = *(const uint2*)(mb3 + t * 2);

        CP_WAIT(1);
        __syncthreads();

        const uint32_t Kbase = smem0 + (9216 + st * 4608) * 2;
        const uint32_t Vbase = smem0 + (18432 + st * 4608) * 2;

        // ---- S = Q @ K^T (ldmatrix K b-frags: 2 n-frags per ldsm4) ----
        float s[2][8][4];
#pragma unroll
        for (int jp = 0; jp < 4; jp++) {
            const int j0 = jp * 2, j1 = j0 + 1;
            s[0][j0][0] = s[0][j0][1] = s[0][j0][2] = s[0][j0][3] = 0.0f;
            s[0][j1][0] = s[0][j1][1] = s[0][j1][2] = s[0][j1][3] = 0.0f;
            s[1][j0][0] = s[1][j0][1] = s[1][j0][2] = s[1][j0][3] = 0.0f;
            s[1][j1][0] = s[1][j1][1] = s[1][j1][2] = s[1][j1][3] = 0.0f;
#pragma unroll
            for (int kk = 0; kk < 4; kk++) {
                uint32_t kf[4];
                ldsm4(kf, Kbase + (boff + jp * 16 * LDH + kk * 16) * 2);
                mma16(s[0][j0], qf[0][kk], kf[0], kf[1]);
                mma16(s[0][j1], qf[0][kk], kf[2], kf[3]);
                mma16(s[1][j0], qf[1][kk], kf[0], kf[1]);
                mma16(s[1][j1], qf[1][kk], kf[2], kf[3]);
            }
        }

        // ---- bitmask ----
#pragma unroll
        for (int mf = 0; mf < 2; mf++) {
#pragma unroll
            for (int j = 0; j < 8; j++) {
                const int bit = (j * 8 + 2 * tig) & 31;
                const uint32_t wa = (j < 4) ? mw[mf * 2].x     : mw[mf * 2].y;
                const uint32_t wb = (j < 4) ? mw[mf * 2 + 1].x : mw[mf * 2 + 1].y;
                if (!((wa >> bit) & 1))       s[mf][j][0] = -1e20f;
                if (!((wa >> (bit + 1)) & 1)) s[mf][j][1] = -1e20f;
                if (!((wb >> bit) & 1))       s[mf][j][2] = -1e20f;
                if (!((wb >> (bit + 1)) & 1)) s[mf][j][3] = -1e20f;
            }
        }

        // ---- online softmax; stage fp16 P into Qs ----
#pragma unroll
        for (int mf = 0; mf < 2; mf++) {
            float mx0 = s[mf][0][0], mx1 = s[mf][0][2];
#pragma unroll
            for (int j = 0; j < 8; j++) {
                mx0 = fmaxf(mx0, fmaxf(s[mf][j][0], s[mf][j][1]));
                mx1 = fmaxf(mx1, fmaxf(s[mf][j][2], s[mf][j][3]));
            }
            mx0 = fmaxf(mx0, __shfl_xor_sync(0xffffffffu, mx0, 1));
            mx0 = fmaxf(mx0, __shfl_xor_sync(0xffffffffu, mx0, 2));
            mx1 = fmaxf(mx1, __shfl_xor_sync(0xffffffffu, mx1, 1));
            mx1 = fmaxf(mx1, __shfl_xor_sync(0xffffffffu, mx1, 2));
            const float mn0 = fmaxf(mi[mf][0], mx0);
            const float mn1 = fmaxf(mi[mf][1], mx1);
            const float a0 = __expf(mi[mf][0] - mn0);
            const float a1 = __expf(mi[mf][1] - mn1);
            float rs0 = 0.0f, rs1 = 0.0f;
            const int rr0 = rb + mf * 16 + g, rr1 = rr0 + 8;
#pragma unroll
            for (int j = 0; j < 8; j++) {
                s[mf][j][0] = __expf(s[mf][j][0] - mn0);
                s[mf][j][1] = __expf(s[mf][j][1] - mn0);
                s[mf][j][2] = __expf(s[mf][j][2] - mn1);
                s[mf][j][3] = __expf(s[mf][j][3] - mn1);
                rs0 += s[mf][j][0] + s[mf][j][1];
                rs1 += s[mf][j][2] + s[mf][j][3];
                *(__half2*)&Qs[rr0 * LDH + j * 8 + 2 * tig] =
                    __floats2half2_rn(s[mf][j][0], s[mf][j][1]);
                *(__half2*)&Qs[rr1 * LDH + j * 8 + 2 * tig] =
                    __floats2half2_rn(s[mf][j][2], s[mf][j][3]);
            }
            rs0 += __shfl_xor_sync(0xffffffffu, rs0, 1);
            rs0 += __shfl_xor_sync(0xffffffffu, rs0, 2);
            rs1 += __shfl_xor_sync(0xffffffffu, rs1, 1);
            rs1 += __shfl_xor_sync(0xffffffffu, rs1, 2);
            li[mf][0] = li[mf][0] * a0 + rs0;
            li[mf][1] = li[mf][1] * a1 + rs1;
            mi[mf][0] = mn0; mi[mf][1] = mn1;
#pragma unroll
            for (int j = 0; j < 8; j++) {
                o[mf][j][0] *= a0; o[mf][j][1] *= a0;
                o[mf][j][2] *= a1; o[mf][j][3] *= a1;
            }
        }
        __syncwarp();

        // ---- O += P @ V (P a-frags + V b-frags via ldmatrix) ----
#pragma unroll
        for (int kk = 0; kk < 4; kk++) {
            uint32_t pa[4], pb[4];
            ldsm4(pa, Qb + (aoff + kk * 16) * 2);               // mf 0 rows
            ldsm4(pb, Qb + (aoff + 16 * LDH + kk * 16) * 2);    // mf 1 rows
#pragma unroll
            for (int jp = 0; jp < 4; jp++) {
                uint32_t vf[4];
                ldsm4(vf, Vbase + (boff + jp * 16 * LDH + kk * 16) * 2);
                mma16(o[0][jp * 2],     pa, vf[0], vf[1]);
                mma16(o[0][jp * 2 + 1], pa, vf[2], vf[3]);
                mma16(o[1][jp * 2],     pb, vf[0], vf[1]);
                mma16(o[1][jp * 2 + 1], pb, vf[2], vf[3]);
            }
        }
        __syncthreads();
    }

    // ---- normalize + write fp16 g_aoh ----
#pragma unroll
    for (int mf = 0; mf < 2; mf++) {
        const int r0 = rb + mf * 16 + g, r1 = r0 + 8;
        const float inv0 = 1.0f / li[mf][0], inv1 = 1.0f / li[mf][1];
        __half* dst0 = g_aoh + ((size_t)b * SS + (q0 + r0)) * DD + h * HD;
        __half* dst1 = g_aoh + ((size_t)b * SS + (q0 + r1)) * DD + h * HD;
#pragma unroll
        for (int j = 0; j < 8; j++) {
            *(__half2*)&dst0[j * 8 + 2 * tig] =
                __floats2half2_rn(o[mf][j][0] * inv0, o[mf][j][1] * inv0);
            *(__half2*)&dst1[j * 8 + 2 * tig] =
                __floats2half2_rn(o[mf][j][2] * inv1, o[mf][j][3] * inv1);
        }
    }
}

// ---------------------------------------------------------------------------
extern "C" void kernel_launch(void* const* d_in, const int* in_sizes, int n_in,
                              void* d_out, int out_size)
{
    const float* x    = (const float*)d_in[0];
    const int*   mask = (const int*)  d_in[1];
    const float* Wqkv = (const float*)d_in[2];
    const float* bqkv = (const float*)d_in[3];
    const float* Wo   = (const float*)d_in[4];
    const float* bo   = (const float*)d_in[5];
    float* out = (float*)d_out;
    (void)in_sizes; (void)n_in; (void)out_size;

    cudaFuncSetAttribute(attn_k, cudaFuncAttributeMaxDynamicSharedMemorySize,
                         ATTN_SMEM);
    cudaFuncSetAttribute(hgemm_k<0>, cudaFuncAttributeMaxDynamicSharedMemorySize,
                         GSMEM);
    cudaFuncSetAttribute(hgemm_k<1>, cudaFuncAttributeMaxDynamicSharedMemorySize,
                         GSMEM);

    // 0) single fused pre-pass
    prepass_k<<<PRE_BLOCKS, 256>>>((const float4*)x, Wqkv, Wo, mask);

    // 1) QKV projection (fp16 mma + ldmatrix) -> fp16 q/k + transposed v
    {
        dim3 grid(3 * DD / 128, (BB * SS) / 128);
        hgemm_k<0><<<grid, 128, GSMEM>>>(bqkv, nullptr, 3 * DD);
    }

    // 2) Flash attention (fp16 mma + ldmatrix) -> g_aoh (fp16)
    attn_k<<<dim3(SS / 128, HH, BB), 128, ATTN_SMEM>>>();

    // 3) Output projection (fp16 mma + ldmatrix) -> d_out (fp32)
    {
        dim3 grid(DD / 128, (BB * SS) / 128);
        hgemm_k<1><<<grid, 128, GSMEM>>>(bo, out, DD);
    }
}

// round 16
// speedup vs baseline: 1.8363x; 1.0185x over previous
#include <cuda_runtime.h>
#include <cuda_fp16.h>
#include <mma.h>
#include <cstdint>

#define BB 4
#define SS 1024
#define DD 1024
#define HH 16
#define HD 64
#define KK 1024

// Scratch (__device__ globals — allocation-free rule)
static __device__ __half g_qh[BB * HH * SS * HD];   // fp16 q, pre-scaled
static __device__ __half g_kh[BB * HH * SS * HD];   // fp16 k
static __device__ __half g_vth[BB * HH * HD * SS];  // fp16 v TRANSPOSED [bh][hd][S]
static __device__ __half g_xh[BB * SS * DD];        // fp16 x [M][K]
static __device__ __half g_wqkvh[3 * DD * DD];      // fp16 Wqkv^T [N][K]
static __device__ __half g_woh[DD * DD];            // fp16 Wo^T   [N][K]
static __device__ __half g_aoh[BB * SS * DD];       // fp16 attn out [M][K]
static __device__ uint32_t g_mb[BB * SS * (SS / 32)];

__device__ __forceinline__ void cpa16(void* dst, const void* src) {
    unsigned d = (unsigned)__cvta_generic_to_shared(dst);
    asm volatile("cp.async.cg.shared.global [%0], [%1], 16;\n" :: "r"(d), "l"(src));
}
#define CP_COMMIT() asm volatile("cp.async.commit_group;\n" ::)
#define CP_WAIT(N)  asm volatile("cp.async.wait_group %0;\n" :: "n"(N))

// fp16 m16n8k16 mma (A row-major, B col-major), fp32 accum, in place
__device__ __forceinline__ void mma16(float* d, const uint32_t* a,
                                      uint32_t b0, uint32_t b1) {
    asm volatile(
        "mma.sync.aligned.m16n8k16.row.col.f32.f16.f16.f32 "
        "{%0,%1,%2,%3}, {%4,%5,%6,%7}, {%8,%9}, {%0,%1,%2,%3};"
        : "+f"(d[0]), "+f"(d[1]), "+f"(d[2]), "+f"(d[3])
        : "r"(a[0]), "r"(a[1]), "r"(a[2]), "r"(a[3]), "r"(b0), "r"(b1));
}

// ldmatrix x4 (non-transposed)
__device__ __forceinline__ void ldsm4(uint32_t* r, uint32_t addr) {
    asm volatile(
        "ldmatrix.sync.aligned.m8n8.x4.shared.b16 {%0,%1,%2,%3}, [%4];"
        : "=r"(r[0]), "=r"(r[1]), "=r"(r[2]), "=r"(r[3]) : "r"(addr));
}

// ---------------------------------------------------------------------------
// Single fused pre-pass (one launch): weight transposes + x->fp16 + mask pack
// ---------------------------------------------------------------------------
#define N4_X  (BB * SS * DD / 4)
#define N_MW  (BB * SS * (SS / 32))
#define TQ_TILES ((3 * DD / 32) * (KK / 32))
#define TO_TILES ((DD / 32) * (KK / 32))
#define LIN_BLOCKS ((N4_X + N_MW + 255) / 256)
#define PRE_BLOCKS (TQ_TILES + TO_TILES + LIN_BLOCKS)

__global__ void __launch_bounds__(256) prepass_k(
    const float4* __restrict__ x4, const float* __restrict__ Wqkv,
    const float* __restrict__ Wo, const int* __restrict__ mask)
{
    __shared__ float tbuf[32][33];
    const int bid = blockIdx.x;
    const int tid = threadIdx.x;

    if (bid < TQ_TILES + TO_TILES) {
        const bool isQ = bid < TQ_TILES;
        const int t = isQ ? bid : bid - TQ_TILES;
        const int C = isQ ? 3 * DD : DD;
        const float* src = isQ ? Wqkv : Wo;
        __half* dst = isQ ? g_wqkvh : g_woh;
        const int bx = (t % (C / 32)) * 32;
        const int by = (t / (C / 32)) * 32;
        const int tx = tid & 31, ty = tid >> 5;
#pragma unroll
        for (int i = 0; i < 4; i++)
            tbuf[ty + i * 8][tx] =
                src[(size_t)(by + ty + i * 8) * C + bx + tx];
        __syncthreads();
#pragma unroll
        for (int i = 0; i < 4; i++)
            dst[(size_t)(bx + ty + i * 8) * KK + by + tx] =
                __float2half_rn(tbuf[tx][ty + i * 8]);
    } else {
        const int i = (bid - TQ_TILES - TO_TILES) * 256 + tid;
        if (i < N4_X) {
            float4 v = x4[i];
            __half2* dst = (__half2*)g_xh + i * 2;
            dst[0] = __floats2half2_rn(v.x, v.y);
            dst[1] = __floats2half2_rn(v.z, v.w);
        } else if (i < N4_X + N_MW) {
            int m = i - N4_X;
            const int4* src = (const int4*)(mask + (size_t)m * 32);
            uint32_t w = 0;
#pragma unroll
            for (int k = 0; k < 8; k++) {
                int4 v = src[k];
                w |= (v.x != 0 ? 1u : 0u) << (k * 4 + 0);
                w |= (v.y != 0 ? 1u : 0u) << (k * 4 + 1);
                w |= (v.z != 0 ? 1u : 0u) << (k * 4 + 2);
                w |= (v.w != 0 ? 1u : 0u) << (k * 4 + 3);
            }
            g_mb[m] = w;
        }
    }
}

// ---------------------------------------------------------------------------
// fp16 mma.sync GEMM, 256 thr (8 warps 2x4, warp tile 64x32). CTA 128x128,
// BK=64, 3-stage cp.async ring, ldmatrix frags (single-buffered — 4
// warps/SMSP provide the latency hiding). Stage: A[128][72]+B[128][72] halfs.
// MODE 0: A=g_xh,  B=g_wqkvh -> fp16 q(*0.125)/k + TRANSPOSED v
// MODE 1: A=g_aoh, B=g_woh   -> C = acc + bias (fp32 final out)
// ---------------------------------------------------------------------------
#define HSTG 18432
#define GSMEM (3 * HSTG * 2)

template <int MODE>
__global__ void __launch_bounds__(256, 2) hgemm_k(
    const float* __restrict__ bias, float* __restrict__ C, int N)
{
    extern __shared__ __half hsm[];

    const int tid = threadIdx.x, lane = tid & 31, warp = tid >> 5;
    const int g = lane >> 2, tig = lane & 3;
    const int wm = (warp >> 2) * 64, wn = (warp & 3) * 32;
    const int m0 = blockIdx.y * 128, n0 = blockIdx.x * 128;

    const __half* Ap = (MODE == 0) ? (const __half*)g_xh : (const __half*)g_aoh;
    const __half* Bp = (MODE == 0) ? (const __half*)g_wqkvh : (const __half*)g_woh;

    const uint32_t smem0 = (uint32_t)__cvta_generic_to_shared(hsm);
    const int aoff = (wm + (lane & 15)) * 72 + (lane >> 4) * 8;
    const int boff = (wn + ((lane >> 4) & 1) * 8 + (lane & 7)) * 72 +
                     ((lane >> 3) & 1) * 8;

    auto issue = [&](int st, int k0) {
        __half* As = hsm + st * HSTG;
        __half* Bs = As + 9216;
#pragma unroll
        for (int v = 0; v < 4; v++) {
            int id = tid + v * 256;           // 0..1023
            int row = id >> 3, c = id & 7;
            cpa16(&As[row * 72 + c * 8],
                  Ap + (size_t)(m0 + row) * KK + k0 + c * 8);
            cpa16(&Bs[row * 72 + c * 8],
                  Bp + (size_t)(n0 + row) * KK + k0 + c * 8);
        }
    };

    float d[4][4][4];
#pragma unroll
    for (int mf = 0; mf < 4; mf++)
#pragma unroll
        for (int nf = 0; nf < 4; nf++)
#pragma unroll
            for (int c = 0; c < 4; c++) d[mf][nf][c] = 0.0f;

    issue(0, 0);  CP_COMMIT();
    issue(1, 64); CP_COMMIT();

    const int NI = KK / 64;
    for (int i = 0; i < NI; i++) {
        const int st = i % 3;
        CP_WAIT(1);
        __syncthreads();
        if (i + 2 < NI) issue((i + 2) % 3, (i + 2) * 64);
        CP_COMMIT();

        const uint32_t Ab = smem0 + (st * HSTG) * 2;
        const uint32_t Aaddr = Ab + aoff * 2;
        const uint32_t Baddr = Ab + 9216 * 2 + boff * 2;

#pragma unroll
        for (int kk = 0; kk < 4; kk++) {
            uint32_t af[4][4], bf[2][4];
#pragma unroll
            for (int mf = 0; mf < 4; mf++)
                ldsm4(af[mf], Aaddr + (mf * 16 * 72 + kk * 16) * 2);
#pragma unroll
            for (int nfp = 0; nfp < 2; nfp++)
                ldsm4(bf[nfp], Baddr + (nfp * 16 * 72 + kk * 16) * 2);
#pragma unroll
            for (int mf = 0; mf < 4; mf++)
#pragma unroll
                for (int nfp = 0; nfp < 2; nfp++) {
                    mma16(d[mf][nfp * 2],     af[mf], bf[nfp][0], bf[nfp][1]);
                    mma16(d[mf][nfp * 2 + 1], af[mf], bf[nfp][2], bf[nfp][3]);
                }
        }
    }

    // ---- epilogue ----
#pragma unroll
    for (int mf = 0; mf < 4; mf++) {
        const int m = m0 + wm + mf * 16 + g;
        const int bb = m >> 10, srow = m & 1023;
#pragma unroll
        for (int nf = 0; nf < 4; nf++) {
            const int col0 = n0 + wn + nf * 8 + 2 * tig;
            const float b0 = bias[col0], b1 = bias[col0 + 1];
            float v0 = d[mf][nf][0] + b0, v1 = d[mf][nf][1] + b1;
            float v2 = d[mf][nf][2] + b0, v3 = d[mf][nf][3] + b1;

            if (MODE == 0) {
                const int h = col0 / 192;
                const int rr = col0 - h * 192;
                const int seg = rr >> 6;
                const int db = rr & 63;
                const size_t bhb = (size_t)(bb * HH + h);
                if (seg == 2) {
                    __half* vd = g_vth + (bhb * HD + db) * SS;
                    vd[srow]          = __float2half_rn(v0);
                    vd[SS + srow]     = __float2half_rn(v1);
                    vd[srow + 8]      = __float2half_rn(v2);
                    vd[SS + srow + 8] = __float2half_rn(v3);
                } else {
                    __half* dst = (seg == 0) ? g_qh : g_kh;
                    const float sc = (seg == 0) ? 0.125f : 1.0f;
                    const size_t idx = (bhb * SS + srow) * HD + db;
                    *(__half2*)&dst[idx] =
                        __floats2half2_rn(v0 * sc, v1 * sc);
                    *(__half2*)&dst[idx + 8 * HD] =
                        __floats2half2_rn(v2 * sc, v3 * sc);
                }
            } else {
                float* dst = C + (size_t)m * N + col0;
                *(float2*)dst           = make_float2(v0, v1);
                *(float2*)(dst + 8 * N) = make_float2(v2, v3);
            }
        }
    }
}

// ---------------------------------------------------------------------------
// Flash attention FA2, fp16 mma + ldmatrix (unchanged from round 15).
// smem halves: Qs[128][72] | Ks[2][64][72] | Vt[2][64][72]. 55296 B.
// ---------------------------------------------------------------------------
#define LDH 72
#define NT (SS / 64)
#define ATTN_SMEM (27648 * 2)

__global__ void __launch_bounds__(128, 2) attn_k(void)
{
    extern __shared__ __half hsm[];
    __half* Qs = hsm;
    __half* Ks = hsm + 9216;
    __half* Vs = hsm + 18432;

    const int tid = threadIdx.x, lane = tid & 31, warp = tid >> 5;
    const int g = lane >> 2, tig = lane & 3;
    const int q0 = blockIdx.x * 128;
    const int h = blockIdx.y, b = blockIdx.z;
    const size_t bh = (size_t)(b * HH + h);
    const __half* qb  = g_qh  + bh * SS * HD;
    const __half* kb  = g_kh  + bh * SS * HD;
    const __half* vtb = g_vth + bh * HD * SS;

    const uint32_t smem0 = (uint32_t)__cvta_generic_to_shared(hsm);
    const uint32_t Qb = smem0;
    const int rb = 32 * warp;
    const int aoff = (rb + (lane & 15)) * LDH + (lane >> 4) * 8;
    const int boff = (((lane >> 4) & 1) * 8 + (lane & 7)) * LDH +
                     ((lane >> 3) & 1) * 8;

#pragma unroll
    for (int j = 0; j < 8; j++) {
        int idx = tid + j * 128;
        int r = idx >> 3, c = idx & 7;
        cpa16(&Qs[r * LDH + c * 8], qb + (size_t)(q0 + r) * HD + c * 8);
    }
#pragma unroll
    for (int j = 0; j < 4; j++) {
        int idx = tid + j * 128;
        int r = idx >> 3, c = idx & 7;
        cpa16(&Ks[r * LDH + c * 8], kb + (size_t)r * HD + c * 8);
        cpa16(&Vs[r * LDH + c * 8], vtb + (size_t)r * SS + c * 8);
    }
    CP_COMMIT();
    CP_WAIT(0);
    __syncthreads();

    uint32_t qf[2][4][4];
#pragma unroll
    for (int mf = 0; mf < 2; mf++)
#pragma unroll
        for (int kk = 0; kk < 4; kk++)
            ldsm4(qf[mf][kk], Qb + (aoff + mf * 16 * LDH + kk * 16) * 2);
    __syncthreads();   // Qs is now the P buffer

    float o[2][8][4];
#pragma unroll
    for (int mf = 0; mf < 2; mf++)
#pragma unroll
        for (int j = 0; j < 8; j++)
#pragma unroll
            for (int c = 0; c < 4; c++) o[mf][j][c] = 0.0f;
    float mi[2][2], li[2][2];
#pragma unroll
    for (int mf = 0; mf < 2; mf++) {
        mi[mf][0] = mi[mf][1] = -1e30f;
        li[mf][0] = li[mf][1] = 0.0f;
    }

    const int r0a = rb + g,      r1a = rb + g + 8;
    const int r0b = rb + 16 + g, r1b = rb + 16 + g + 8;
    const uint32_t* mb0 = g_mb + ((size_t)b * SS + (q0 + r0a)) * 32;
    const uint32_t* mb1 = g_mb + ((size_t)b * SS + (q0 + r1a)) * 32;
    const uint32_t* mb2 = g_mb + ((size_t)b * SS + (q0 + r0b)) * 32;
    const uint32_t* mb3 = g_mb + ((size_t)b * SS + (q0 + r1b)) * 32;

    for (int t = 0; t < NT; t++) {
        const int st = t & 1;
        if (t + 1 < NT) {
            const __half* kb2  = kb  + (size_t)(t + 1) * 64 * HD;
            const __half* vtb2 = vtb + (size_t)(t + 1) * 64;
            __half* Kd = Ks + (st ^ 1) * 4608;
            __half* Vd = Vs + (st ^ 1) * 4608;
#pragma unroll
            for (int j = 0; j < 4; j++) {
                int idx = tid + j * 128;
                int r = idx >> 3, c = idx & 7;
                cpa16(&Kd[r * LDH + c * 8], kb2 + (size_t)r * HD + c * 8);
                cpa16(&Vd[r * LDH + c * 8], vtb2 + (size_t)r * SS + c * 8);
            }
        }
        CP_COMMIT();

        uint2 mw[4];
        mw[0] = *(const uint2*)(mb0 + t * 2);
        mw[1] = *(const uint2*)(mb1 + t * 2);
        mw[2] = *(const uint2*)(mb2 + t * 2);
        mw[3] = *(const uint2*)(mb3 + t * 2);

        CP_WAIT(1);
        __syncthreads();

        const uint32_t Kbase = smem0 + (9216 + st * 4608) * 2;
        const uint32_t Vbase = smem0 + (18432 + st * 4608) * 2;

        float s[2][8][4];
#pragma unroll
        for (int jp = 0; jp < 4; jp++) {
            const int j0 = jp * 2, j1 = j0 + 1;
            s[0][j0][0] = s[0][j0][1] = s[0][j0][2] = s[0][j0][3] = 0.0f;
            s[0][j1][0] = s[0][j1][1] = s[0][j1][2] = s[0][j1][3] = 0.0f;
            s[1][j0][0] = s[1][j0][1] = s[1][j0][2] = s[1][j0][3] = 0.0f;
            s[1][j1][0] = s[1][j1][1] = s[1][j1][2] = s[1][j1][3] = 0.0f;
#pragma unroll
            for (int kk = 0; kk < 4; kk++) {
                uint32_t kf[4];
                ldsm4(kf, Kbase + (boff + jp * 16 * LDH + kk * 16) * 2);
                mma16(s[0][j0], qf[0][kk], kf[0], kf[1]);
                mma16(s[0][j1], qf[0][kk], kf[2], kf[3]);
                mma16(s[1][j0], qf[1][kk], kf[0], kf[1]);
                mma16(s[1][j1], qf[1][kk], kf[2], kf[3]);
            }
        }

#pragma unroll
        for (int mf = 0; mf < 2; mf++) {
#pragma unroll
            for (int j = 0; j < 8; j++) {
                const int bit = (j * 8 + 2 * tig) & 31;
                const uint32_t wa = (j < 4) ? mw[mf * 2].x     : mw[mf * 2].y;
                const uint32_t wb = (j < 4) ? mw[mf * 2 + 1].x : mw[mf * 2 + 1].y;
                if (!((wa >> bit) & 1))       s[mf][j][0] = -1e20f;
                if (!((wa >> (bit + 1)) & 1)) s[mf][j][1] = -1e20f;
                if (!((wb >> bit) & 1))       s[mf][j][2] = -1e20f;
                if (!((wb >> (bit + 1)) & 1)) s[mf][j][3] = -1e20f;
            }
        }

#pragma unroll
        for (int mf = 0; mf < 2; mf++) {
            float mx0 = s[mf][0][0], mx1 = s[mf][0][2];
#pragma unroll
            for (int j = 0; j < 8; j++) {
                mx0 = fmaxf(mx0, fmaxf(s[mf][j][0], s[mf][j][1]));
                mx1 = fmaxf(mx1, fmaxf(s[mf][j][2], s[mf][j][3]));
            }
            mx0 = fmaxf(mx0, __shfl_xor_sync(0xffffffffu, mx0, 1));
            mx0 = fmaxf(mx0, __shfl_xor_sync(0xffffffffu, mx0, 2));
            mx1 = fmaxf(mx1, __shfl_xor_sync(0xffffffffu, mx1, 1));
            mx1 = fmaxf(mx1, __shfl_xor_sync(0xffffffffu, mx1, 2));
            const float mn0 = fmaxf(mi[mf][0], mx0);
            const float mn1 = fmaxf(mi[mf][1], mx1);
            const float a0 = __expf(mi[mf][0] - mn0);
            const float a1 = __expf(mi[mf][1] - mn1);
            float rs0 = 0.0f, rs1 = 0.0f;
            const int rr0 = rb + mf * 16 + g, rr1 = rr0 + 8;
#pragma unroll
            for (int j = 0; j < 8; j++) {
                s[mf][j][0] = __expf(s[mf][j][0] - mn0);
                s[mf][j][1] = __expf(s[mf][j][1] - mn0);
                s[mf][j][2] = __expf(s[mf][j][2] - mn1);
                s[mf][j][3] = __expf(s[mf][j][3] - mn1);
                rs0 += s[mf][j][0] + s[mf][j][1];
                rs1 += s[mf][j][2] + s[mf][j][3];
                *(__half2*)&Qs[rr0 * LDH + j * 8 + 2 * tig] =
                    __floats2half2_rn(s[mf][j][0], s[mf][j][1]);
                *(__half2*)&Qs[rr1 * LDH + j * 8 + 2 * tig] =
                    __floats2half2_rn(s[mf][j][2], s[mf][j][3]);
            }
            rs0 += __shfl_xor_sync(0xffffffffu, rs0, 1);
            rs0 += __shfl_xor_sync(0xffffffffu, rs0, 2);
            rs1 += __shfl_xor_sync(0xffffffffu, rs1, 1);
            rs1 += __shfl_xor_sync(0xffffffffu, rs1, 2);
            li[mf][0] = li[mf][0] * a0 + rs0;
            li[mf][1] = li[mf][1] * a1 + rs1;
            mi[mf][0] = mn0; mi[mf][1] = mn1;
#pragma unroll
            for (int j = 0; j < 8; j++) {
                o[mf][j][0] *= a0; o[mf][j][1] *= a0;
                o[mf][j][2] *= a1; o[mf][j][3] *= a1;
            }
        }
        __syncwarp();

#pragma unroll
        for (int kk = 0; kk < 4; kk++) {
            uint32_t pa[4], pb[4];
            ldsm4(pa, Qb + (aoff + kk * 16) * 2);
            ldsm4(pb, Qb + (aoff + 16 * LDH + kk * 16) * 2);
#pragma unroll
            for (int jp = 0; jp < 4; jp++) {
                uint32_t vf[4];
                ldsm4(vf, Vbase + (boff + jp * 16 * LDH + kk * 16) * 2);
                mma16(o[0][jp * 2],     pa, vf[0], vf[1]);
                mma16(o[0][jp * 2 + 1], pa, vf[2], vf[3]);
                mma16(o[1][jp * 2],     pb, vf[0], vf[1]);
                mma16(o[1][jp * 2 + 1], pb, vf[2], vf[3]);
            }
        }
        __syncthreads();
    }

#pragma unroll
    for (int mf = 0; mf < 2; mf++) {
        const int r0 = rb + mf * 16 + g, r1 = r0 + 8;
        const float inv0 = 1.0f / li[mf][0], inv1 = 1.0f / li[mf][1];
        __half* dst0 = g_aoh + ((size_t)b * SS + (q0 + r0)) * DD + h * HD;
        __half* dst1 = g_aoh + ((size_t)b * SS + (q0 + r1)) * DD + h * HD;
#pragma unroll
        for (int j = 0; j < 8; j++) {
            *(__half2*)&dst0[j * 8 + 2 * tig] =
                __floats2half2_rn(o[mf][j][0] * inv0, o[mf][j][1] * inv0);
            *(__half2*)&dst1[j * 8 + 2 * tig] =
                __floats2half2_rn(o[mf][j][2] * inv1, o[mf][j][3] * inv1);
        }
    }
}

// ---------------------------------------------------------------------------
extern "C" void kernel_launch(void* const* d_in, const int* in_sizes, int n_in,
                              void* d_out, int out_size)
{
    const float* x    = (const float*)d_in[0];
    const int*   mask = (const int*)  d_in[1];
    const float* Wqkv = (const float*)d_in[2];
    const float* bqkv = (const float*)d_in[3];
    const float* Wo   = (const float*)d_in[4];
    const float* bo   = (const float*)d_in[5];
    float* out = (float*)d_out;
    (void)in_sizes; (void)n_in; (void)out_size;

    cudaFuncSetAttribute(attn_k, cudaFuncAttributeMaxDynamicSharedMemorySize,
                         ATTN_SMEM);
    cudaFuncSetAttribute(hgemm_k<0>, cudaFuncAttributeMaxDynamicSharedMemorySize,
                         GSMEM);
    cudaFuncSetAttribute(hgemm_k<1>, cudaFuncAttributeMaxDynamicSharedMemorySize,
                         GSMEM);

    // 0) single fused pre-pass
    prepass_k<<<PRE_BLOCKS, 256>>>((const float4*)x, Wqkv, Wo, mask);

    // 1) QKV projection -> fp16 q/k + transposed v
    {
        dim3 grid(3 * DD / 128, (BB * SS) / 128);
        hgemm_k<0><<<grid, 256, GSMEM>>>(bqkv, nullptr, 3 * DD);
    }

    // 2) Flash attention -> g_aoh (fp16)
    attn_k<<<dim3(SS / 128, HH, BB), 128, ATTN_SMEM>>>();

    // 3) Output projection -> d_out (fp32)
    {
        dim3 grid(DD / 128, (BB * SS) / 128);
        hgemm_k<1><<<grid, 256, GSMEM>>>(bo, out, DD);
    }
}